// round 6
// baseline (speedup 1.0000x reference)
#include <cuda_runtime.h>
#include <cuda_bf16.h>
#include <math.h>
#include <stdint.h>

// ---------------- problem constants ----------------
#define Bq_ 4
#define Sq_ 1024
#define Vq_ 50257
#define VPAD_ 50304
#define Dq_ 768
#define Hq_ 3072
#define NHq_ 12
#define DHq_ 64
#define Lq_ 12
#define Mq_ (Bq_*Sq_)   // 4096 rows

typedef __nv_bfloat16 bf16;

#define WSQ (768UL*768UL)
#define WSH (768UL*3072UL)
#define LWBLK (4UL*WSQ + 2UL*WSH)
#define WOUT_OFF (LWBLK*12UL)
#define WTOT (WOUT_OFF + (size_t)VPAD_*Dq_)

// ---------------- scratch (device globals; no allocs allowed) ----------------
__device__ float g_h[Mq_*Dq_];
__device__ bf16 g_ahi[Mq_*Dq_], g_alo[Mq_*Dq_];
__device__ bf16 g_qhi[Mq_*Dq_], g_qlo[Mq_*Dq_];
__device__ bf16 g_khi[Mq_*Dq_], g_klo[Mq_*Dq_];
__device__ bf16 g_vhi[Mq_*Dq_], g_vlo[Mq_*Dq_];
__device__ bf16 g_ohi[Mq_*Dq_], g_olo[Mq_*Dq_];
__device__ bf16 g_fhi[Mq_*Hq_], g_flo[Mq_*Hq_];
__device__ bf16 g_whi[WTOT], g_wlo[WTOT];

// ---------------- helpers ----------------
__device__ __forceinline__ uint32_t s2u(const void* p) {
    return (uint32_t)__cvta_generic_to_shared(p);
}
__device__ __forceinline__ void cp16(uint32_t d, const void* s) {
    asm volatile("cp.async.cg.shared.global [%0], [%1], 16;\n" :: "r"(d), "l"(s) : "memory");
}
#define CP_COMMIT asm volatile("cp.async.commit_group;\n" ::: "memory")
#define CP_WAIT1  asm volatile("cp.async.wait_group 1;\n" ::: "memory")
#define CP_WAIT0  asm volatile("cp.async.wait_group 0;\n" ::: "memory")

__device__ __forceinline__ void ldsm4(uint32_t &r0, uint32_t &r1, uint32_t &r2, uint32_t &r3,
                                      uint32_t addr) {
    asm volatile("ldmatrix.sync.aligned.m8n8.x4.shared.b16 {%0,%1,%2,%3}, [%4];\n"
        : "=r"(r0), "=r"(r1), "=r"(r2), "=r"(r3) : "r"(addr));
}
__device__ __forceinline__ void ldsm4t(uint32_t &r0, uint32_t &r1, uint32_t &r2, uint32_t &r3,
                                       uint32_t addr) {
    asm volatile("ldmatrix.sync.aligned.m8n8.x4.trans.shared.b16 {%0,%1,%2,%3}, [%4];\n"
        : "=r"(r0), "=r"(r1), "=r"(r2), "=r"(r3) : "r"(addr));
}
__device__ __forceinline__ void mma_bf16(float* c, uint32_t a0, uint32_t a1, uint32_t a2, uint32_t a3,
                                         uint32_t b0, uint32_t b1) {
    asm volatile("mma.sync.aligned.m16n8k16.row.col.f32.bf16.bf16.f32 "
        "{%0,%1,%2,%3},{%4,%5,%6,%7},{%8,%9},{%0,%1,%2,%3};\n"
        : "+f"(c[0]), "+f"(c[1]), "+f"(c[2]), "+f"(c[3])
        : "r"(a0), "r"(a1), "r"(a2), "r"(a3), "r"(b0), "r"(b1));
}
__device__ __forceinline__ void split2(float x, bf16& h, bf16& l) {
    h = __float2bfloat16(x);
    l = __float2bfloat16(x - __bfloat162float(h));
}
__device__ __forceinline__ uint32_t packbf2(float a, float b) {
    __nv_bfloat162 t = __floats2bfloat162_rn(a, b);
    return *(uint32_t*)&t;
}

// ---------------- weight transpose + split (batched variants) ----------------
__device__ __forceinline__ void tsplit_body(const float* __restrict__ W, bf16* __restrict__ hi,
                                            bf16* __restrict__ lo, int K, int Nsrc) {
    __shared__ float tile[32][33];
    int k0 = blockIdx.y * 32, n0 = blockIdx.x * 32;
    int tx = threadIdx.x, ty = threadIdx.y;
    #pragma unroll
    for (int i = 0; i < 4; i++) {
        int k = k0 + ty + i * 8, n = n0 + tx;
        tile[ty + i * 8][tx] = (n < Nsrc) ? W[(long)k * Nsrc + n] : 0.f;
    }
    __syncthreads();
    #pragma unroll
    for (int i = 0; i < 4; i++) {
        int n = n0 + ty + i * 8, k = k0 + tx;
        float v = tile[tx][ty + i * 8];
        bf16 h, l; split2(v, h, l);
        hi[(long)n * K + k] = h;
        lo[(long)n * K + k] = l;
    }
}

__global__ void tsplit_sq_kernel(const float* __restrict__ Wq, const float* __restrict__ Wk,
                                 const float* __restrict__ Wv, const float* __restrict__ Wo,
                                 bf16* __restrict__ hi, bf16* __restrict__ lo) {
    int z = blockIdx.z, layer = z >> 2, which = z & 3;
    const float* W = (which == 0 ? Wq : which == 1 ? Wk : which == 2 ? Wv : Wo) + (size_t)layer * WSQ;
    size_t off = (size_t)layer * LWBLK + (size_t)which * WSQ;
    tsplit_body(W, hi + off, lo + off, 768, 768);
}
__global__ void tsplit_w1_kernel(const float* __restrict__ W1, bf16* __restrict__ hi, bf16* __restrict__ lo) {
    int layer = blockIdx.z;
    size_t off = (size_t)layer * LWBLK + 4 * WSQ;
    tsplit_body(W1 + (size_t)layer * WSH, hi + off, lo + off, 768, Hq_);
}
__global__ void tsplit_w2_kernel(const float* __restrict__ W2, bf16* __restrict__ hi, bf16* __restrict__ lo) {
    int layer = blockIdx.z;
    size_t off = (size_t)layer * LWBLK + 4 * WSQ + WSH;
    tsplit_body(W2 + (size_t)layer * WSH, hi + off, lo + off, Hq_, 768);
}
__global__ void tsplit_out_kernel(const float* __restrict__ W, bf16* __restrict__ hi, bf16* __restrict__ lo) {
    tsplit_body(W, hi + WOUT_OFF, lo + WOUT_OFF, 768, Vq_);
}

// ---------------- embedding ----------------
__global__ void embed_kernel(const int* __restrict__ x,
                             const float* __restrict__ tok,
                             const float* __restrict__ pos,
                             float* __restrict__ h) {
    int row = blockIdx.x;
    int s = row & (Sq_ - 1);
    int tid = x[row];
    const float* tp = tok + (long)tid * Dq_;
    const float* pp = pos + (long)s * Dq_;
    float* hp = h + (long)row * Dq_;
    for (int d = threadIdx.x; d < Dq_; d += 256)
        hp[d] = tp[d] + pp[d];
}

// ---------------- layernorm -> bf16 hi/lo split output ----------------
__global__ void ln_kernel(const float* __restrict__ X,
                          const float* __restrict__ w,
                          const float* __restrict__ bb,
                          bf16* __restrict__ Yhi, bf16* __restrict__ Ylo) {
    int row = blockIdx.x;
    const float* x = X + (long)row * Dq_;
    int t = threadIdx.x;
    float v0 = x[t], v1 = x[t + 256], v2 = x[t + 512];

    __shared__ float red[8];
    __shared__ float mean_s, inv_s;

    float s = v0 + v1 + v2;
    #pragma unroll
    for (int o = 16; o > 0; o >>= 1) s += __shfl_down_sync(0xffffffffu, s, o);
    if ((t & 31) == 0) red[t >> 5] = s;
    __syncthreads();
    if (t == 0) {
        float tot = 0.f;
        #pragma unroll
        for (int i = 0; i < 8; i++) tot += red[i];
        mean_s = tot * (1.0f / Dq_);
    }
    __syncthreads();
    float mean = mean_s;
    float d0 = v0 - mean, d1 = v1 - mean, d2 = v2 - mean;
    float q = d0 * d0 + d1 * d1 + d2 * d2;
    #pragma unroll
    for (int o = 16; o > 0; o >>= 1) q += __shfl_down_sync(0xffffffffu, q, o);
    if ((t & 31) == 0) red[t >> 5] = q;
    __syncthreads();
    if (t == 0) {
        float tot = 0.f;
        #pragma unroll
        for (int i = 0; i < 8; i++) tot += red[i];
        inv_s = rsqrtf(tot * (1.0f / Dq_) + 1e-5f);
    }
    __syncthreads();
    float inv = inv_s;
    long base = (long)row * Dq_;
    #pragma unroll
    for (int i = 0; i < 3; i++) {
        int c = t + i * 256;
        float dd = (i == 0 ? d0 : i == 1 ? d1 : d2);
        float y = dd * inv * w[c] + bb[c];
        bf16 h, l; split2(y, h, l);
        Yhi[base + c] = h;
        Ylo[base + c] = l;
    }
}

// ---------------- bf16x3 HMMA GEMM, 3-stage cp.async pipeline ----------------
// C = A[MxK] * B^T (B stored [N][K] hi/lo bf16) + bias
// EPI: 0 = fp32 C; 1 = GELU -> split bf16; 2 = fp32 residual add in-place; 3 = split bf16
// SWAP: bm from blockIdx.x (use for huge-N logits GEMM so B tiles get L2 reuse)
#define GEMM_SMEM (3 * 4 * 128 * 40 * 2)   // 122880

template<int EPI, bool SWAP>
__device__ __forceinline__ void gemm_body(
    const bf16* __restrict__ Ahi, const bf16* __restrict__ Alo,
    const bf16* __restrict__ Bhi, const bf16* __restrict__ Blo,
    const float* __restrict__ bias,
    float* __restrict__ C, bf16* __restrict__ Chi, bf16* __restrict__ Clo,
    int K, int N, int Nout)
{
    extern __shared__ bf16 sm[];   // [3 buf][4 arr][128][40]
    uint32_t smb = s2u(sm);
    int tid = threadIdx.x;
    int bm = (SWAP ? blockIdx.x : blockIdx.y) * 128;
    int bn = (SWAP ? blockIdx.y : blockIdx.x) * 128;
    int warp = tid >> 5, lane = tid & 31;
    int wm = warp >> 2, wn = warp & 3;

    float acc[4][4][4];
    #pragma unroll
    for (int i = 0; i < 4; i++)
        #pragma unroll
        for (int j = 0; j < 4; j++)
            #pragma unroll
            for (int k = 0; k < 4; k++) acc[i][j][k] = 0.f;

    const bf16* srcs[4] = { Ahi + (long)bm * K, Alo + (long)bm * K,
                            Bhi + (long)bn * K, Blo + (long)bn * K };

    auto issue = [&](int b, int kt) {
        int k0 = kt * 32;
        #pragma unroll
        for (int arr = 0; arr < 4; arr++) {
            #pragma unroll
            for (int i = 0; i < 2; i++) {
                int ch = tid + i * 256;
                int row = ch >> 2, cg = ch & 3;
                uint32_t dst = smb + ((((b * 4 + arr) * 128 + row) * 40) + cg * 8) * 2;
                cp16(dst, srcs[arr] + (long)row * K + k0 + cg * 8);
            }
        }
    };

    int nk = K >> 5;
    issue(0, 0); CP_COMMIT;
    issue(1, 1); CP_COMMIT;   // nk >= 24 always here

    int lrow = lane & 15, lcg = lane >> 4;

    for (int kt = 0; kt < nk; ++kt) {
        int cur = kt % 3;
        if (kt + 1 < nk) { CP_WAIT1; } else { CP_WAIT0; }
        __syncthreads();
        if (kt + 2 < nk) { issue((kt + 2) % 3, kt + 2); CP_COMMIT; }

        #pragma unroll
        for (int ks = 0; ks < 2; ++ks) {
            uint32_t ah[4][4], al[4][4];
            #pragma unroll
            for (int mf = 0; mf < 4; mf++) {
                int row = wm * 64 + mf * 16 + lrow;
                int col = ks * 16 + lcg * 8;
                uint32_t a0 = smb + ((((cur * 4 + 0) * 128 + row) * 40) + col) * 2;
                uint32_t a1 = smb + ((((cur * 4 + 1) * 128 + row) * 40) + col) * 2;
                ldsm4(ah[mf][0], ah[mf][1], ah[mf][2], ah[mf][3], a0);
                ldsm4(al[mf][0], al[mf][1], al[mf][2], al[mf][3], a1);
            }
            uint32_t bh[2][4], bl[2][4];
            #pragma unroll
            for (int nf2 = 0; nf2 < 2; nf2++) {
                int row = wn * 32 + nf2 * 16 + lrow;
                int col = ks * 16 + lcg * 8;
                uint32_t b0 = smb + ((((cur * 4 + 2) * 128 + row) * 40) + col) * 2;
                uint32_t b1 = smb + ((((cur * 4 + 3) * 128 + row) * 40) + col) * 2;
                ldsm4(bh[nf2][0], bh[nf2][1], bh[nf2][2], bh[nf2][3], b0);
                ldsm4(bl[nf2][0], bl[nf2][1], bl[nf2][2], bl[nf2][3], b1);
            }
            #pragma unroll
            for (int mf = 0; mf < 4; mf++) {
                #pragma unroll
                for (int nf = 0; nf < 4; nf++) {
                    int g = nf >> 1, o = nf & 1;
                    uint32_t b0h = bh[g][o], b1h = bh[g][o + 2];
                    uint32_t b0l = bl[g][o], b1l = bl[g][o + 2];
                    float* c = acc[mf][nf];
                    mma_bf16(c, ah[mf][0], ah[mf][1], ah[mf][2], ah[mf][3], b0h, b1h);
                    mma_bf16(c, ah[mf][0], ah[mf][1], ah[mf][2], ah[mf][3], b0l, b1l);
                    mma_bf16(c, al[mf][0], al[mf][1], al[mf][2], al[mf][3], b0h, b1h);
                }
            }
        }
        // no trailing sync: buffer 'cur' is only rewritten at kt+3; the per-iteration
        // syncs at kt+1 and kt+2 order all warps' reads before that issue.
    }

    int r = lane >> 2, c2 = (lane & 3) * 2;
    #pragma unroll
    for (int mf = 0; mf < 4; mf++) {
        #pragma unroll
        for (int nf = 0; nf < 4; nf++) {
            #pragma unroll
            for (int half = 0; half < 2; half++) {
                long row = bm + wm * 64 + mf * 16 + r + half * 8;
                #pragma unroll
                for (int e = 0; e < 2; e++) {
                    int col = bn + wn * 32 + nf * 8 + c2 + e;
                    if (col < Nout) {
                        float v = acc[mf][nf][half * 2 + e] + bias[col];
                        if (EPI == 1 || EPI == 3) {
                            if (EPI == 1)
                                v = 0.5f * v * (1.f + erff(v * 0.70710678118654752f));
                            bf16 h, l; split2(v, h, l);
                            Chi[row * N + col] = h;
                            Clo[row * N + col] = l;
                        } else if (EPI == 2) {
                            v += C[row * (long)Nout + col];
                            C[row * (long)Nout + col] = v;
                        } else {
                            C[row * (long)Nout + col] = v;
                        }
                    }
                }
            }
        }
    }
}

template<int EPI, bool SWAP>
__global__ __launch_bounds__(256, 1) void gemm_kernel(
    const bf16* __restrict__ Ahi, const bf16* __restrict__ Alo,
    const bf16* __restrict__ Bhi, const bf16* __restrict__ Blo,
    const float* __restrict__ bias,
    float* __restrict__ C, bf16* __restrict__ Chi, bf16* __restrict__ Clo,
    int K, int N, int Nout)
{
    gemm_body<EPI, SWAP>(Ahi, Alo, Bhi, Blo, bias, C, Chi, Clo, K, N, Nout);
}

__global__ __launch_bounds__(256, 1) void gemm_qkv_kernel(
    const bf16* __restrict__ Ahi, const bf16* __restrict__ Alo,
    const bf16* __restrict__ whi, const bf16* __restrict__ wlo,
    const float* __restrict__ bq, const float* __restrict__ bk, const float* __restrict__ bv,
    bf16* __restrict__ qhi, bf16* __restrict__ qlo,
    bf16* __restrict__ khi, bf16* __restrict__ klo,
    bf16* __restrict__ vhi, bf16* __restrict__ vlo)
{
    int z = blockIdx.z;
    const bf16* Bh = whi + (size_t)z * WSQ;
    const bf16* Bl = wlo + (size_t)z * WSQ;
    const float* bias = (z == 0) ? bq : (z == 1) ? bk : bv;
    bf16* Chi = (z == 0) ? qhi : (z == 1) ? khi : vhi;
    bf16* Clo = (z == 0) ? qlo : (z == 1) ? klo : vlo;
    gemm_body<3, false>(Ahi, Alo, Bh, Bl, bias, nullptr, Chi, Clo, Dq_, Dq_, Dq_);
}

// ---------------- HMMA flash attention (round-5 proven) ----------------
#define AT_STRIDE 72
#define AT_TILE (64 * AT_STRIDE)
#define ATTN_SMEM (6 * AT_TILE * 2)

__global__ __launch_bounds__(128, 4) void attn_kernel(
    const bf16* __restrict__ Qh_g, const bf16* __restrict__ Ql_g,
    const bf16* __restrict__ Kh_g, const bf16* __restrict__ Kl_g,
    const bf16* __restrict__ Vh_g, const bf16* __restrict__ Vl_g,
    bf16* __restrict__ Ohi, bf16* __restrict__ Olo)
{
    extern __shared__ bf16 asm_[];
    uint32_t smb = s2u(asm_);
    uint32_t sQh = smb;
    uint32_t sQl = sQh + AT_TILE * 2;
    uint32_t sKh = sQl + AT_TILE * 2;
    uint32_t sKl = sKh + AT_TILE * 2;
    uint32_t sVh = sKl + AT_TILE * 2;
    uint32_t sVl = sVh + AT_TILE * 2;

    int t = threadIdx.x, warp = t >> 5, lane = t & 31;
    int q0 = blockIdx.x * 64, h = blockIdx.y, b = blockIdx.z;

    long rowbase = (long)(b * Sq_ + q0) * Dq_ + h * DHq_;

    #pragma unroll
    for (int i = 0; i < 4; i++) {
        int idx = t + i * 128;
        int row = idx >> 3, ch = idx & 7;
        uint32_t doff = (uint32_t)(row * AT_STRIDE + ch * 8) * 2;
        cp16(sQh + doff, Qh_g + rowbase + (long)row * Dq_ + ch * 8);
        cp16(sQl + doff, Ql_g + rowbase + (long)row * Dq_ + ch * 8);
    }

    float m[2] = { -1e30f, -1e30f }, l[2] = { 0.f, 0.f };
    float oacc[8][4];
    #pragma unroll
    for (int i = 0; i < 8; i++)
        #pragma unroll
        for (int j = 0; j < 4; j++) oacc[i][j] = 0.f;

    int lrow = lane & 15, lcg = lane >> 4;

    for (int j0 = 0; j0 <= q0; j0 += 64) {
        long kbase = (long)(b * Sq_ + j0) * Dq_ + h * DHq_;
        #pragma unroll
        for (int i = 0; i < 4; i++) {
            int idx = t + i * 128;
            int row = idx >> 3, ch = idx & 7;
            uint32_t doff = (uint32_t)(row * AT_STRIDE + ch * 8) * 2;
            long goff = kbase + (long)row * Dq_ + ch * 8;
            cp16(sKh + doff, Kh_g + goff);
            cp16(sKl + doff, Kl_g + goff);
            cp16(sVh + doff, Vh_g + goff);
            cp16(sVl + doff, Vl_g + goff);
        }
        CP_COMMIT; CP_WAIT0;
        __syncthreads();

        float sacc[8][4];
        #pragma unroll
        for (int i = 0; i < 8; i++)
            #pragma unroll
            for (int j = 0; j < 4; j++) sacc[i][j] = 0.f;

        #pragma unroll
        for (int ks = 0; ks < 4; ++ks) {
            int acol = ks * 16 + lcg * 8;
            uint32_t qh[4], ql[4];
            uint32_t qaddr = (uint32_t)((warp * 16 + lrow) * AT_STRIDE + acol) * 2;
            ldsm4(qh[0], qh[1], qh[2], qh[3], sQh + qaddr);
            ldsm4(ql[0], ql[1], ql[2], ql[3], sQl + qaddr);
            #pragma unroll
            for (int kg = 0; kg < 4; ++kg) {
                uint32_t kh[4], kl[4];
                uint32_t kaddr = (uint32_t)((kg * 16 + lrow) * AT_STRIDE + acol) * 2;
                ldsm4(kh[0], kh[1], kh[2], kh[3], sKh + kaddr);
                ldsm4(kl[0], kl[1], kl[2], kl[3], sKl + kaddr);
                #pragma unroll
                for (int o = 0; o < 2; ++o) {
                    float* c = sacc[kg * 2 + o];
                    mma_bf16(c, qh[0], qh[1], qh[2], qh[3], kh[o], kh[o + 2]);
                    mma_bf16(c, qh[0], qh[1], qh[2], qh[3], kl[o], kl[o + 2]);
                    mma_bf16(c, ql[0], ql[1], ql[2], ql[3], kh[o], kh[o + 2]);
                }
            }
        }

        int r0loc = warp * 16 + (lane >> 2);
        bool diag = (j0 == q0);
        float mx[2] = { -1e30f, -1e30f };
        #pragma unroll
        for (int nf = 0; nf < 8; nf++) {
            #pragma unroll
            for (int i = 0; i < 4; i++) {
                float v = sacc[nf][i] * 0.125f;
                if (diag) {
                    int col = nf * 8 + (lane & 3) * 2 + (i & 1);
                    int row = r0loc + ((i >> 1) ? 8 : 0);
                    if (col > row) v = -1e30f;
                }
                sacc[nf][i] = v;
                mx[i >> 1] = fmaxf(mx[i >> 1], v);
            }
        }
        #pragma unroll
        for (int o = 1; o < 4; o <<= 1) {
            mx[0] = fmaxf(mx[0], __shfl_xor_sync(0xffffffffu, mx[0], o));
            mx[1] = fmaxf(mx[1], __shfl_xor_sync(0xffffffffu, mx[1], o));
        }
        float fac[2], sum[2] = { 0.f, 0.f };
        #pragma unroll
        for (int j = 0; j < 2; j++) {
            float mnew = fmaxf(m[j], mx[j]);
            fac[j] = __expf(m[j] - mnew);
            m[j] = mnew;
        }
        #pragma unroll
        for (int nf = 0; nf < 8; nf++) {
            #pragma unroll
            for (int i = 0; i < 4; i++) {
                float p = __expf(sacc[nf][i] - m[i >> 1]);
                sacc[nf][i] = p;
                sum[i >> 1] += p;
            }
        }
        #pragma unroll
        for (int o = 1; o < 4; o <<= 1) {
            sum[0] += __shfl_xor_sync(0xffffffffu, sum[0], o);
            sum[1] += __shfl_xor_sync(0xffffffffu, sum[1], o);
        }
        #pragma unroll
        for (int j = 0; j < 2; j++) l[j] = l[j] * fac[j] + sum[j];
        #pragma unroll
        for (int nf = 0; nf < 8; nf++) {
            oacc[nf][0] *= fac[0]; oacc[nf][1] *= fac[0];
            oacc[nf][2] *= fac[1]; oacc[nf][3] *= fac[1];
        }

        #pragma unroll
        for (int t2 = 0; t2 < 4; ++t2) {
            float* p0 = sacc[2 * t2];
            float* p1 = sacc[2 * t2 + 1];
            bf16 h00, h01, h02, h03, h10, h11, h12, h13;
            h00 = __float2bfloat16(p0[0]); h01 = __float2bfloat16(p0[1]);
            h02 = __float2bfloat16(p0[2]); h03 = __float2bfloat16(p0[3]);
            h10 = __float2bfloat16(p1[0]); h11 = __float2bfloat16(p1[1]);
            h12 = __float2bfloat16(p1[2]); h13 = __float2bfloat16(p1[3]);
            uint32_t pah[4], pal[4];
            pah[0] = packbf2(__bfloat162float(h00), __bfloat162float(h01));
            pah[1] = packbf2(__bfloat162float(h02), __bfloat162float(h03));
            pah[2] = packbf2(__bfloat162float(h10), __bfloat162float(h11));
            pah[3] = packbf2(__bfloat162float(h12), __bfloat162float(h13));
            pal[0] = packbf2(p0[0] - __bfloat162float(h00), p0[1] - __bfloat162float(h01));
            pal[1] = packbf2(p0[2] - __bfloat162float(h02), p0[3] - __bfloat162float(h03));
            pal[2] = packbf2(p1[0] - __bfloat162float(h10), p1[1] - __bfloat162float(h11));
            pal[3] = packbf2(p1[2] - __bfloat162float(h12), p1[3] - __bfloat162float(h13));

            #pragma unroll
            for (int nd = 0; nd < 4; ++nd) {
                uint32_t vrow = (uint32_t)(t2 * 16 + ((lane >> 4) << 3) + (lane & 7));
                uint32_t vcol = (uint32_t)(nd * 16 + (((lane >> 3) & 1) << 3));
                uint32_t vaddr = (vrow * AT_STRIDE + vcol) * 2;
                uint32_t vh[4], vl[4];
                ldsm4t(vh[0], vh[1], vh[2], vh[3], sVh + vaddr);
                ldsm4t(vl[0], vl[1], vl[2], vl[3], sVl + vaddr);
                #pragma unroll
                for (int o = 0; o < 2; ++o) {
                    float* c = oacc[nd * 2 + o];
                    mma_bf16(c, pah[0], pah[1], pah[2], pah[3], vh[o], vh[o + 2]);
                    mma_bf16(c, pah[0], pah[1], pah[2], pah[3], vl[o], vl[o + 2]);
                    mma_bf16(c, pal[0], pal[1], pal[2], pal[3], vh[o], vh[o + 2]);
                }
            }
        }
        __syncthreads();
    }

    float inv0 = 1.f / l[0], inv1 = 1.f / l[1];
    long row0 = (long)(b * Sq_ + q0 + warp * 16 + (lane >> 2));
    long row1 = row0 + 8;
    #pragma unroll
    for (int nf = 0; nf < 8; nf++) {
        int col = h * DHq_ + nf * 8 + (lane & 3) * 2;
        float v0 = oacc[nf][0] * inv0, v1 = oacc[nf][1] * inv0;
        float v2 = oacc[nf][2] * inv1, v3 = oacc[nf][3] * inv1;
        bf16 h0, l0, h1, l1, h2, l2, h3, l3;
        split2(v0, h0, l0); split2(v1, h1, l1);
        split2(v2, h2, l2); split2(v3, h3, l3);
        *(__nv_bfloat162*)&Ohi[row0 * Dq_ + col] = __nv_bfloat162(h0, h1);
        *(__nv_bfloat162*)&Olo[row0 * Dq_ + col] = __nv_bfloat162(l0, l1);
        *(__nv_bfloat162*)&Ohi[row1 * Dq_ + col] = __nv_bfloat162(h2, h3);
        *(__nv_bfloat162*)&Olo[row1 * Dq_ + col] = __nv_bfloat162(l2, l3);
    }
}

// ---------------- launcher ----------------
extern "C" void kernel_launch(void* const* d_in, const int* in_sizes, int n_in,
                              void* d_out, int out_size) {
    const int*   x    = (const int*)  d_in[0];
    const float* tok  = (const float*)d_in[1];
    const float* pos  = (const float*)d_in[2];
    const float* Wq   = (const float*)d_in[3];
    const float* bq   = (const float*)d_in[4];
    const float* Wk   = (const float*)d_in[5];
    const float* bk   = (const float*)d_in[6];
    const float* Wv   = (const float*)d_in[7];
    const float* bv   = (const float*)d_in[8];
    const float* Wo   = (const float*)d_in[9];
    const float* bo   = (const float*)d_in[10];
    const float* ln1w = (const float*)d_in[11];
    const float* ln1b = (const float*)d_in[12];
    const float* ln2w = (const float*)d_in[13];
    const float* ln2b = (const float*)d_in[14];
    const float* W1   = (const float*)d_in[15];
    const float* b1   = (const float*)d_in[16];
    const float* W2   = (const float*)d_in[17];
    const float* b2   = (const float*)d_in[18];
    const float* lnfw = (const float*)d_in[19];
    const float* lnfb = (const float*)d_in[20];
    const float* Wout = (const float*)d_in[21];
    const float* bout = (const float*)d_in[22];
    float* out = (float*)d_out;

    float *h;
    bf16 *ahi, *alo, *qhi, *qlo, *khi, *klo, *vhi, *vlo, *ohi, *olo, *fhi, *flo, *whi, *wlo;
    cudaGetSymbolAddress((void**)&h, g_h);
    cudaGetSymbolAddress((void**)&ahi, g_ahi);
    cudaGetSymbolAddress((void**)&alo, g_alo);
    cudaGetSymbolAddress((void**)&qhi, g_qhi);
    cudaGetSymbolAddress((void**)&qlo, g_qlo);
    cudaGetSymbolAddress((void**)&khi, g_khi);
    cudaGetSymbolAddress((void**)&klo, g_klo);
    cudaGetSymbolAddress((void**)&vhi, g_vhi);
    cudaGetSymbolAddress((void**)&vlo, g_vlo);
    cudaGetSymbolAddress((void**)&ohi, g_ohi);
    cudaGetSymbolAddress((void**)&olo, g_olo);
    cudaGetSymbolAddress((void**)&fhi, g_fhi);
    cudaGetSymbolAddress((void**)&flo, g_flo);
    cudaGetSymbolAddress((void**)&whi, g_whi);
    cudaGetSymbolAddress((void**)&wlo, g_wlo);

    cudaFuncSetAttribute((const void*)gemm_kernel<0,false>, cudaFuncAttributeMaxDynamicSharedMemorySize, GEMM_SMEM);
    cudaFuncSetAttribute((const void*)gemm_kernel<0,true>,  cudaFuncAttributeMaxDynamicSharedMemorySize, GEMM_SMEM);
    cudaFuncSetAttribute((const void*)gemm_kernel<1,false>, cudaFuncAttributeMaxDynamicSharedMemorySize, GEMM_SMEM);
    cudaFuncSetAttribute((const void*)gemm_kernel<2,false>, cudaFuncAttributeMaxDynamicSharedMemorySize, GEMM_SMEM);
    cudaFuncSetAttribute((const void*)gemm_qkv_kernel, cudaFuncAttributeMaxDynamicSharedMemorySize, GEMM_SMEM);
    cudaFuncSetAttribute((const void*)attn_kernel, cudaFuncAttributeMaxDynamicSharedMemorySize, ATTN_SMEM);

    // ---- weight prep (batched) ----
    dim3 tb(32, 8);
    tsplit_sq_kernel<<<dim3(24, 24, 48), tb>>>(Wq, Wk, Wv, Wo, whi, wlo);
    tsplit_w1_kernel<<<dim3(Hq_ / 32, 24, 12), tb>>>(W1, whi, wlo);
    tsplit_w2_kernel<<<dim3(24, Hq_ / 32, 12), tb>>>(W2, whi, wlo);
    tsplit_out_kernel<<<dim3(VPAD_ / 32, 24), tb>>>(Wout, whi, wlo);

    embed_kernel<<<Mq_, 256>>>(x, tok, pos, h);

    dim3 gD(Dq_ / 128, Mq_ / 128);
    dim3 gH(Hq_ / 128, Mq_ / 128);
    dim3 gVsw(Mq_ / 128, VPAD_ / 128);   // SWAP grid: x = m-tiles, y = n-tiles
    dim3 gQKV(Dq_ / 128, Mq_ / 128, 3);
    dim3 gAtt(Sq_ / 64, NHq_, Bq_);

    for (int i = 0; i < Lq_; ++i) {
        size_t off = (size_t)i * LWBLK;
        ln_kernel<<<Mq_, 256>>>(h, ln1w + i * Dq_, ln1b + i * Dq_, ahi, alo);
        gemm_qkv_kernel<<<gQKV, 256, GEMM_SMEM>>>(ahi, alo, whi + off, wlo + off,
            bq + i * Dq_, bk + i * Dq_, bv + i * Dq_,
            qhi, qlo, khi, klo, vhi, vlo);
        attn_kernel<<<gAtt, 128, ATTN_SMEM>>>(qhi, qlo, khi, klo, vhi, vlo, ohi, olo);
        gemm_kernel<2,false><<<gD, 256, GEMM_SMEM>>>(ohi, olo, whi + off + 3 * WSQ, wlo + off + 3 * WSQ,
            bo + i * Dq_, h, nullptr, nullptr, Dq_, Dq_, Dq_);
        ln_kernel<<<Mq_, 256>>>(h, ln2w + i * Dq_, ln2b + i * Dq_, ahi, alo);
        gemm_kernel<1,false><<<gH, 256, GEMM_SMEM>>>(ahi, alo, whi + off + 4 * WSQ, wlo + off + 4 * WSQ,
            b1 + i * Hq_, nullptr, fhi, flo, Dq_, Hq_, Hq_);
        gemm_kernel<2,false><<<gD, 256, GEMM_SMEM>>>(fhi, flo, whi + off + 4 * WSQ + WSH, wlo + off + 4 * WSQ + WSH,
            b2 + i * Dq_, h, nullptr, nullptr, Hq_, Dq_, Dq_);
    }

    ln_kernel<<<Mq_, 256>>>(h, lnfw, lnfb, ahi, alo);
    gemm_kernel<0,true><<<gVsw, 256, GEMM_SMEM>>>(ahi, alo, whi + WOUT_OFF, wlo + WOUT_OFF,
        bout, out, nullptr, nullptr, Dq_, VPAD_, Vq_);
}

// round 7
// speedup vs baseline: 1.0095x; 1.0095x over previous
#include <cuda_runtime.h>
#include <cuda_bf16.h>
#include <math.h>
#include <stdint.h>

// ---------------- problem constants ----------------
#define Bq_ 4
#define Sq_ 1024
#define Vq_ 50257
#define VPAD_ 50304
#define Dq_ 768
#define Hq_ 3072
#define NHq_ 12
#define DHq_ 64
#define Lq_ 12
#define Mq_ (Bq_*Sq_)   // 4096 rows

typedef __nv_bfloat16 bf16;

#define WSQ (768UL*768UL)
#define WSH (768UL*3072UL)
#define LWBLK (4UL*WSQ + 2UL*WSH)
#define WOUT_OFF (LWBLK*12UL)
#define WTOT (WOUT_OFF + (size_t)VPAD_*Dq_)

// ---------------- scratch (device globals; no allocs allowed) ----------------
__device__ float g_h[Mq_*Dq_];
__device__ bf16 g_ahi[Mq_*Dq_], g_alo[Mq_*Dq_];
__device__ bf16 g_qhi[Mq_*Dq_], g_qlo[Mq_*Dq_];
__device__ bf16 g_khi[Mq_*Dq_], g_klo[Mq_*Dq_];
__device__ bf16 g_vhi[Mq_*Dq_], g_vlo[Mq_*Dq_];
__device__ bf16 g_ohi[Mq_*Dq_], g_olo[Mq_*Dq_];
__device__ bf16 g_fhi[Mq_*Hq_], g_flo[Mq_*Hq_];
__device__ bf16 g_whi[WTOT], g_wlo[WTOT];

// ---------------- helpers ----------------
__device__ __forceinline__ uint32_t s2u(const void* p) {
    return (uint32_t)__cvta_generic_to_shared(p);
}
__device__ __forceinline__ void cp16(uint32_t d, const void* s) {
    asm volatile("cp.async.cg.shared.global [%0], [%1], 16;\n" :: "r"(d), "l"(s) : "memory");
}
#define CP_COMMIT asm volatile("cp.async.commit_group;\n" ::: "memory")
#define CP_WAIT1  asm volatile("cp.async.wait_group 1;\n" ::: "memory")
#define CP_WAIT0  asm volatile("cp.async.wait_group 0;\n" ::: "memory")

__device__ __forceinline__ void ldsm4(uint32_t &r0, uint32_t &r1, uint32_t &r2, uint32_t &r3,
                                      uint32_t addr) {
    asm volatile("ldmatrix.sync.aligned.m8n8.x4.shared.b16 {%0,%1,%2,%3}, [%4];\n"
        : "=r"(r0), "=r"(r1), "=r"(r2), "=r"(r3) : "r"(addr));
}
__device__ __forceinline__ void ldsm4t(uint32_t &r0, uint32_t &r1, uint32_t &r2, uint32_t &r3,
                                       uint32_t addr) {
    asm volatile("ldmatrix.sync.aligned.m8n8.x4.trans.shared.b16 {%0,%1,%2,%3}, [%4];\n"
        : "=r"(r0), "=r"(r1), "=r"(r2), "=r"(r3) : "r"(addr));
}
__device__ __forceinline__ void mma_bf16(float* c, uint32_t a0, uint32_t a1, uint32_t a2, uint32_t a3,
                                         uint32_t b0, uint32_t b1) {
    asm volatile("mma.sync.aligned.m16n8k16.row.col.f32.bf16.bf16.f32 "
        "{%0,%1,%2,%3},{%4,%5,%6,%7},{%8,%9},{%0,%1,%2,%3};\n"
        : "+f"(c[0]), "+f"(c[1]), "+f"(c[2]), "+f"(c[3])
        : "r"(a0), "r"(a1), "r"(a2), "r"(a3), "r"(b0), "r"(b1));
}
__device__ __forceinline__ void split2(float x, bf16& h, bf16& l) {
    h = __float2bfloat16(x);
    l = __float2bfloat16(x - __bfloat162float(h));
}
__device__ __forceinline__ uint32_t packbf2(float a, float b) {
    __nv_bfloat162 t = __floats2bfloat162_rn(a, b);
    return *(uint32_t*)&t;
}

// ---------------- weight transpose + split (batched variants) ----------------
__device__ __forceinline__ void tsplit_body(const float* __restrict__ W, bf16* __restrict__ hi,
                                            bf16* __restrict__ lo, int K, int Nsrc) {
    __shared__ float tile[32][33];
    int k0 = blockIdx.y * 32, n0 = blockIdx.x * 32;
    int tx = threadIdx.x, ty = threadIdx.y;
    #pragma unroll
    for (int i = 0; i < 4; i++) {
        int k = k0 + ty + i * 8, n = n0 + tx;
        tile[ty + i * 8][tx] = (n < Nsrc) ? W[(long)k * Nsrc + n] : 0.f;
    }
    __syncthreads();
    #pragma unroll
    for (int i = 0; i < 4; i++) {
        int n = n0 + ty + i * 8, k = k0 + tx;
        float v = tile[tx][ty + i * 8];
        bf16 h, l; split2(v, h, l);
        hi[(long)n * K + k] = h;
        lo[(long)n * K + k] = l;
    }
}

__global__ void tsplit_sq_kernel(const float* __restrict__ Wq, const float* __restrict__ Wk,
                                 const float* __restrict__ Wv, const float* __restrict__ Wo,
                                 bf16* __restrict__ hi, bf16* __restrict__ lo) {
    int z = blockIdx.z, layer = z >> 2, which = z & 3;
    const float* W = (which == 0 ? Wq : which == 1 ? Wk : which == 2 ? Wv : Wo) + (size_t)layer * WSQ;
    size_t off = (size_t)layer * LWBLK + (size_t)which * WSQ;
    tsplit_body(W, hi + off, lo + off, 768, 768);
}
__global__ void tsplit_w1_kernel(const float* __restrict__ W1, bf16* __restrict__ hi, bf16* __restrict__ lo) {
    int layer = blockIdx.z;
    size_t off = (size_t)layer * LWBLK + 4 * WSQ;
    tsplit_body(W1 + (size_t)layer * WSH, hi + off, lo + off, 768, Hq_);
}
__global__ void tsplit_w2_kernel(const float* __restrict__ W2, bf16* __restrict__ hi, bf16* __restrict__ lo) {
    int layer = blockIdx.z;
    size_t off = (size_t)layer * LWBLK + 4 * WSQ + WSH;
    tsplit_body(W2 + (size_t)layer * WSH, hi + off, lo + off, Hq_, 768);
}
__global__ void tsplit_out_kernel(const float* __restrict__ W, bf16* __restrict__ hi, bf16* __restrict__ lo) {
    tsplit_body(W, hi + WOUT_OFF, lo + WOUT_OFF, 768, Vq_);
}

// ---------------- embedding ----------------
__global__ void embed_kernel(const int* __restrict__ x,
                             const float* __restrict__ tok,
                             const float* __restrict__ pos,
                             float* __restrict__ h) {
    int row = blockIdx.x;
    int s = row & (Sq_ - 1);
    int tid = x[row];
    const float* tp = tok + (long)tid * Dq_;
    const float* pp = pos + (long)s * Dq_;
    float* hp = h + (long)row * Dq_;
    for (int d = threadIdx.x; d < Dq_; d += 256)
        hp[d] = tp[d] + pp[d];
}

// ---------------- layernorm -> bf16 hi/lo split output ----------------
__global__ void ln_kernel(const float* __restrict__ X,
                          const float* __restrict__ w,
                          const float* __restrict__ bb,
                          bf16* __restrict__ Yhi, bf16* __restrict__ Ylo) {
    int row = blockIdx.x;
    const float* x = X + (long)row * Dq_;
    int t = threadIdx.x;
    float v0 = x[t], v1 = x[t + 256], v2 = x[t + 512];

    __shared__ float red[8];
    __shared__ float mean_s, inv_s;

    float s = v0 + v1 + v2;
    #pragma unroll
    for (int o = 16; o > 0; o >>= 1) s += __shfl_down_sync(0xffffffffu, s, o);
    if ((t & 31) == 0) red[t >> 5] = s;
    __syncthreads();
    if (t == 0) {
        float tot = 0.f;
        #pragma unroll
        for (int i = 0; i < 8; i++) tot += red[i];
        mean_s = tot * (1.0f / Dq_);
    }
    __syncthreads();
    float mean = mean_s;
    float d0 = v0 - mean, d1 = v1 - mean, d2 = v2 - mean;
    float q = d0 * d0 + d1 * d1 + d2 * d2;
    #pragma unroll
    for (int o = 16; o > 0; o >>= 1) q += __shfl_down_sync(0xffffffffu, q, o);
    if ((t & 31) == 0) red[t >> 5] = q;
    __syncthreads();
    if (t == 0) {
        float tot = 0.f;
        #pragma unroll
        for (int i = 0; i < 8; i++) tot += red[i];
        inv_s = rsqrtf(tot * (1.0f / Dq_) + 1e-5f);
    }
    __syncthreads();
    float inv = inv_s;
    long base = (long)row * Dq_;
    #pragma unroll
    for (int i = 0; i < 3; i++) {
        int c = t + i * 256;
        float dd = (i == 0 ? d0 : i == 1 ? d1 : d2);
        float y = dd * inv * w[c] + bb[c];
        bf16 h, l; split2(y, h, l);
        Yhi[base + c] = h;
        Ylo[base + c] = l;
    }
}

// ---------------- bf16x3 HMMA GEMM, 3-stage pipeline, TERM-MAJOR mma order ----------------
// C = A[MxK] * B^T (B stored [N][K] hi/lo bf16) + bias
// EPI: 0 = fp32 C; 1 = GELU -> split bf16; 2 = fp32 residual add in-place; 3 = split bf16
#define GEMM_SMEM (3 * 4 * 128 * 40 * 2)   // 122880

template<int EPI, bool SWAP>
__device__ __forceinline__ void gemm_body(
    const bf16* __restrict__ Ahi, const bf16* __restrict__ Alo,
    const bf16* __restrict__ Bhi, const bf16* __restrict__ Blo,
    const float* __restrict__ bias,
    float* __restrict__ C, bf16* __restrict__ Chi, bf16* __restrict__ Clo,
    int K, int N, int Nout)
{
    extern __shared__ bf16 sm[];   // [3 buf][4 arr][128][40]
    uint32_t smb = s2u(sm);
    int tid = threadIdx.x;
    int bm = (SWAP ? blockIdx.x : blockIdx.y) * 128;
    int bn = (SWAP ? blockIdx.y : blockIdx.x) * 128;
    int warp = tid >> 5, lane = tid & 31;
    int wm = warp >> 2, wn = warp & 3;

    float acc[4][4][4];
    #pragma unroll
    for (int i = 0; i < 4; i++)
        #pragma unroll
        for (int j = 0; j < 4; j++)
            #pragma unroll
            for (int k = 0; k < 4; k++) acc[i][j][k] = 0.f;

    const bf16* srcs[4] = { Ahi + (long)bm * K, Alo + (long)bm * K,
                            Bhi + (long)bn * K, Blo + (long)bn * K };

    auto issue = [&](int b, int kt) {
        int k0 = kt * 32;
        #pragma unroll
        for (int arr = 0; arr < 4; arr++) {
            #pragma unroll
            for (int i = 0; i < 2; i++) {
                int ch = tid + i * 256;
                int row = ch >> 2, cg = ch & 3;
                uint32_t dst = smb + ((((b * 4 + arr) * 128 + row) * 40) + cg * 8) * 2;
                cp16(dst, srcs[arr] + (long)row * K + k0 + cg * 8);
            }
        }
    };

    int nk = K >> 5;
    issue(0, 0); CP_COMMIT;
    issue(1, 1); CP_COMMIT;

    int lrow = lane & 15, lcg = lane >> 4;

    for (int kt = 0; kt < nk; ++kt) {
        int cur = kt % 3;
        if (kt + 1 < nk) { CP_WAIT1; } else { CP_WAIT0; }
        __syncthreads();
        if (kt + 2 < nk) { issue((kt + 2) % 3, kt + 2); CP_COMMIT; }

        #pragma unroll
        for (int ks = 0; ks < 2; ++ks) {
            uint32_t ah[4][4], al[4][4];
            #pragma unroll
            for (int mf = 0; mf < 4; mf++) {
                int row = wm * 64 + mf * 16 + lrow;
                int col = ks * 16 + lcg * 8;
                uint32_t a0 = smb + ((((cur * 4 + 0) * 128 + row) * 40) + col) * 2;
                uint32_t a1 = smb + ((((cur * 4 + 1) * 128 + row) * 40) + col) * 2;
                ldsm4(ah[mf][0], ah[mf][1], ah[mf][2], ah[mf][3], a0);
                ldsm4(al[mf][0], al[mf][1], al[mf][2], al[mf][3], a1);
            }
            uint32_t bh[2][4], bl[2][4];
            #pragma unroll
            for (int nf2 = 0; nf2 < 2; nf2++) {
                int row = wn * 32 + nf2 * 16 + lrow;
                int col = ks * 16 + lcg * 8;
                uint32_t b0 = smb + ((((cur * 4 + 2) * 128 + row) * 40) + col) * 2;
                uint32_t b1 = smb + ((((cur * 4 + 3) * 128 + row) * 40) + col) * 2;
                ldsm4(bh[nf2][0], bh[nf2][1], bh[nf2][2], bh[nf2][3], b0);
                ldsm4(bl[nf2][0], bl[nf2][1], bl[nf2][2], bl[nf2][3], b1);
            }
            // TERM-MAJOR: pass 1 (Ah*Bh) over all 16 independent accumulators,
            // then pass 2 (Ah*Bl), then pass 3 (Al*Bh). Consecutive asm stmts are
            // independent, so the tensor pipe never stalls on accumulator RAW.
            #pragma unroll
            for (int mf = 0; mf < 4; mf++)
                #pragma unroll
                for (int nf = 0; nf < 4; nf++) {
                    int g = nf >> 1, o = nf & 1;
                    mma_bf16(acc[mf][nf], ah[mf][0], ah[mf][1], ah[mf][2], ah[mf][3],
                             bh[g][o], bh[g][o + 2]);
                }
            #pragma unroll
            for (int mf = 0; mf < 4; mf++)
                #pragma unroll
                for (int nf = 0; nf < 4; nf++) {
                    int g = nf >> 1, o = nf & 1;
                    mma_bf16(acc[mf][nf], ah[mf][0], ah[mf][1], ah[mf][2], ah[mf][3],
                             bl[g][o], bl[g][o + 2]);
                }
            #pragma unroll
            for (int mf = 0; mf < 4; mf++)
                #pragma unroll
                for (int nf = 0; nf < 4; nf++) {
                    int g = nf >> 1, o = nf & 1;
                    mma_bf16(acc[mf][nf], al[mf][0], al[mf][1], al[mf][2], al[mf][3],
                             bh[g][o], bh[g][o + 2]);
                }
        }
    }

    int r = lane >> 2, c2 = (lane & 3) * 2;
    #pragma unroll
    for (int mf = 0; mf < 4; mf++) {
        #pragma unroll
        for (int nf = 0; nf < 4; nf++) {
            #pragma unroll
            for (int half = 0; half < 2; half++) {
                long row = bm + wm * 64 + mf * 16 + r + half * 8;
                #pragma unroll
                for (int e = 0; e < 2; e++) {
                    int col = bn + wn * 32 + nf * 8 + c2 + e;
                    if (col < Nout) {
                        float v = acc[mf][nf][half * 2 + e] + bias[col];
                        if (EPI == 1 || EPI == 3) {
                            if (EPI == 1)
                                v = 0.5f * v * (1.f + erff(v * 0.70710678118654752f));
                            bf16 h, l; split2(v, h, l);
                            Chi[row * N + col] = h;
                            Clo[row * N + col] = l;
                        } else if (EPI == 2) {
                            v += C[row * (long)Nout + col];
                            C[row * (long)Nout + col] = v;
                        } else {
                            C[row * (long)Nout + col] = v;
                        }
                    }
                }
            }
        }
    }
}

template<int EPI, bool SWAP>
__global__ __launch_bounds__(256, 1) void gemm_kernel(
    const bf16* __restrict__ Ahi, const bf16* __restrict__ Alo,
    const bf16* __restrict__ Bhi, const bf16* __restrict__ Blo,
    const float* __restrict__ bias,
    float* __restrict__ C, bf16* __restrict__ Chi, bf16* __restrict__ Clo,
    int K, int N, int Nout)
{
    gemm_body<EPI, SWAP>(Ahi, Alo, Bhi, Blo, bias, C, Chi, Clo, K, N, Nout);
}

__global__ __launch_bounds__(256, 1) void gemm_qkv_kernel(
    const bf16* __restrict__ Ahi, const bf16* __restrict__ Alo,
    const bf16* __restrict__ whi, const bf16* __restrict__ wlo,
    const float* __restrict__ bq, const float* __restrict__ bk, const float* __restrict__ bv,
    bf16* __restrict__ qhi, bf16* __restrict__ qlo,
    bf16* __restrict__ khi, bf16* __restrict__ klo,
    bf16* __restrict__ vhi, bf16* __restrict__ vlo)
{
    int z = blockIdx.z;
    const bf16* Bh = whi + (size_t)z * WSQ;
    const bf16* Bl = wlo + (size_t)z * WSQ;
    const float* bias = (z == 0) ? bq : (z == 1) ? bk : bv;
    bf16* Chi = (z == 0) ? qhi : (z == 1) ? khi : vhi;
    bf16* Clo = (z == 0) ? qlo : (z == 1) ? klo : vlo;
    gemm_body<3, false>(Ahi, Alo, Bh, Bl, bias, nullptr, Chi, Clo, Dq_, Dq_, Dq_);
}

// ---------------- HMMA flash attention, term-major mma order ----------------
#define AT_STRIDE 72
#define AT_TILE (64 * AT_STRIDE)
#define ATTN_SMEM (6 * AT_TILE * 2)

__global__ __launch_bounds__(128, 3) void attn_kernel(
    const bf16* __restrict__ Qh_g, const bf16* __restrict__ Ql_g,
    const bf16* __restrict__ Kh_g, const bf16* __restrict__ Kl_g,
    const bf16* __restrict__ Vh_g, const bf16* __restrict__ Vl_g,
    bf16* __restrict__ Ohi, bf16* __restrict__ Olo)
{
    extern __shared__ bf16 asm_[];
    uint32_t smb = s2u(asm_);
    uint32_t sQh = smb;
    uint32_t sQl = sQh + AT_TILE * 2;
    uint32_t sKh = sQl + AT_TILE * 2;
    uint32_t sKl = sKh + AT_TILE * 2;
    uint32_t sVh = sKl + AT_TILE * 2;
    uint32_t sVl = sVh + AT_TILE * 2;

    int t = threadIdx.x, warp = t >> 5, lane = t & 31;
    int q0 = blockIdx.x * 64, h = blockIdx.y, b = blockIdx.z;

    long rowbase = (long)(b * Sq_ + q0) * Dq_ + h * DHq_;

    #pragma unroll
    for (int i = 0; i < 4; i++) {
        int idx = t + i * 128;
        int row = idx >> 3, ch = idx & 7;
        uint32_t doff = (uint32_t)(row * AT_STRIDE + ch * 8) * 2;
        cp16(sQh + doff, Qh_g + rowbase + (long)row * Dq_ + ch * 8);
        cp16(sQl + doff, Ql_g + rowbase + (long)row * Dq_ + ch * 8);
    }

    float m[2] = { -1e30f, -1e30f }, l[2] = { 0.f, 0.f };
    float oacc[8][4];
    #pragma unroll
    for (int i = 0; i < 8; i++)
        #pragma unroll
        for (int j = 0; j < 4; j++) oacc[i][j] = 0.f;

    int lrow = lane & 15, lcg = lane >> 4;

    for (int j0 = 0; j0 <= q0; j0 += 64) {
        long kbase = (long)(b * Sq_ + j0) * Dq_ + h * DHq_;
        #pragma unroll
        for (int i = 0; i < 4; i++) {
            int idx = t + i * 128;
            int row = idx >> 3, ch = idx & 7;
            uint32_t doff = (uint32_t)(row * AT_STRIDE + ch * 8) * 2;
            long goff = kbase + (long)row * Dq_ + ch * 8;
            cp16(sKh + doff, Kh_g + goff);
            cp16(sKl + doff, Kl_g + goff);
            cp16(sVh + doff, Vh_g + goff);
            cp16(sVl + doff, Vl_g + goff);
        }
        CP_COMMIT; CP_WAIT0;
        __syncthreads();

        float sacc[8][4];
        #pragma unroll
        for (int i = 0; i < 8; i++)
            #pragma unroll
            for (int j = 0; j < 4; j++) sacc[i][j] = 0.f;

        #pragma unroll
        for (int ks = 0; ks < 4; ++ks) {
            int acol = ks * 16 + lcg * 8;
            uint32_t qh[4], ql[4];
            uint32_t qaddr = (uint32_t)((warp * 16 + lrow) * AT_STRIDE + acol) * 2;
            ldsm4(qh[0], qh[1], qh[2], qh[3], sQh + qaddr);
            ldsm4(ql[0], ql[1], ql[2], ql[3], sQl + qaddr);
            uint32_t kh[4][4], kl[4][4];
            #pragma unroll
            for (int kg = 0; kg < 4; ++kg) {
                uint32_t kaddr = (uint32_t)((kg * 16 + lrow) * AT_STRIDE + acol) * 2;
                ldsm4(kh[kg][0], kh[kg][1], kh[kg][2], kh[kg][3], sKh + kaddr);
                ldsm4(kl[kg][0], kl[kg][1], kl[kg][2], kl[kg][3], sKl + kaddr);
            }
            // term-major: 8 independent accumulators per pass
            #pragma unroll
            for (int kg = 0; kg < 4; ++kg)
                #pragma unroll
                for (int o = 0; o < 2; ++o)
                    mma_bf16(sacc[kg * 2 + o], qh[0], qh[1], qh[2], qh[3], kh[kg][o], kh[kg][o + 2]);
            #pragma unroll
            for (int kg = 0; kg < 4; ++kg)
                #pragma unroll
                for (int o = 0; o < 2; ++o)
                    mma_bf16(sacc[kg * 2 + o], qh[0], qh[1], qh[2], qh[3], kl[kg][o], kl[kg][o + 2]);
            #pragma unroll
            for (int kg = 0; kg < 4; ++kg)
                #pragma unroll
                for (int o = 0; o < 2; ++o)
                    mma_bf16(sacc[kg * 2 + o], ql[0], ql[1], ql[2], ql[3], kh[kg][o], kh[kg][o + 2]);
        }

        int r0loc = warp * 16 + (lane >> 2);
        bool diag = (j0 == q0);
        float mx[2] = { -1e30f, -1e30f };
        #pragma unroll
        for (int nf = 0; nf < 8; nf++) {
            #pragma unroll
            for (int i = 0; i < 4; i++) {
                float v = sacc[nf][i] * 0.125f;
                if (diag) {
                    int col = nf * 8 + (lane & 3) * 2 + (i & 1);
                    int row = r0loc + ((i >> 1) ? 8 : 0);
                    if (col > row) v = -1e30f;
                }
                sacc[nf][i] = v;
                mx[i >> 1] = fmaxf(mx[i >> 1], v);
            }
        }
        #pragma unroll
        for (int o = 1; o < 4; o <<= 1) {
            mx[0] = fmaxf(mx[0], __shfl_xor_sync(0xffffffffu, mx[0], o));
            mx[1] = fmaxf(mx[1], __shfl_xor_sync(0xffffffffu, mx[1], o));
        }
        float fac[2], sum[2] = { 0.f, 0.f };
        #pragma unroll
        for (int j = 0; j < 2; j++) {
            float mnew = fmaxf(m[j], mx[j]);
            fac[j] = __expf(m[j] - mnew);
            m[j] = mnew;
        }
        #pragma unroll
        for (int nf = 0; nf < 8; nf++) {
            #pragma unroll
            for (int i = 0; i < 4; i++) {
                float p = __expf(sacc[nf][i] - m[i >> 1]);
                sacc[nf][i] = p;
                sum[i >> 1] += p;
            }
        }
        #pragma unroll
        for (int o = 1; o < 4; o <<= 1) {
            sum[0] += __shfl_xor_sync(0xffffffffu, sum[0], o);
            sum[1] += __shfl_xor_sync(0xffffffffu, sum[1], o);
        }
        #pragma unroll
        for (int j = 0; j < 2; j++) l[j] = l[j] * fac[j] + sum[j];
        #pragma unroll
        for (int nf = 0; nf < 8; nf++) {
            oacc[nf][0] *= fac[0]; oacc[nf][1] *= fac[0];
            oacc[nf][2] *= fac[1]; oacc[nf][3] *= fac[1];
        }

        #pragma unroll
        for (int t2 = 0; t2 < 4; ++t2) {
            float* p0 = sacc[2 * t2];
            float* p1 = sacc[2 * t2 + 1];
            bf16 h00, h01, h02, h03, h10, h11, h12, h13;
            h00 = __float2bfloat16(p0[0]); h01 = __float2bfloat16(p0[1]);
            h02 = __float2bfloat16(p0[2]); h03 = __float2bfloat16(p0[3]);
            h10 = __float2bfloat16(p1[0]); h11 = __float2bfloat16(p1[1]);
            h12 = __float2bfloat16(p1[2]); h13 = __float2bfloat16(p1[3]);
            uint32_t pah[4], pal[4];
            pah[0] = packbf2(__bfloat162float(h00), __bfloat162float(h01));
            pah[1] = packbf2(__bfloat162float(h02), __bfloat162float(h03));
            pah[2] = packbf2(__bfloat162float(h10), __bfloat162float(h11));
            pah[3] = packbf2(__bfloat162float(h12), __bfloat162float(h13));
            pal[0] = packbf2(p0[0] - __bfloat162float(h00), p0[1] - __bfloat162float(h01));
            pal[1] = packbf2(p0[2] - __bfloat162float(h02), p0[3] - __bfloat162float(h03));
            pal[2] = packbf2(p1[0] - __bfloat162float(h10), p1[1] - __bfloat162float(h11));
            pal[3] = packbf2(p1[2] - __bfloat162float(h12), p1[3] - __bfloat162float(h13));

            uint32_t vh[4][4], vl[4][4];
            #pragma unroll
            for (int nd = 0; nd < 4; ++nd) {
                uint32_t vrow = (uint32_t)(t2 * 16 + ((lane >> 4) << 3) + (lane & 7));
                uint32_t vcol = (uint32_t)(nd * 16 + (((lane >> 3) & 1) << 3));
                uint32_t vaddr = (vrow * AT_STRIDE + vcol) * 2;
                ldsm4t(vh[nd][0], vh[nd][1], vh[nd][2], vh[nd][3], sVh + vaddr);
                ldsm4t(vl[nd][0], vl[nd][1], vl[nd][2], vl[nd][3], sVl + vaddr);
            }
            // term-major over 8 independent output accumulators
            #pragma unroll
            for (int nd = 0; nd < 4; ++nd)
                #pragma unroll
                for (int o = 0; o < 2; ++o)
                    mma_bf16(oacc[nd * 2 + o], pah[0], pah[1], pah[2], pah[3], vh[nd][o], vh[nd][o + 2]);
            #pragma unroll
            for (int nd = 0; nd < 4; ++nd)
                #pragma unroll
                for (int o = 0; o < 2; ++o)
                    mma_bf16(oacc[nd * 2 + o], pah[0], pah[1], pah[2], pah[3], vl[nd][o], vl[nd][o + 2]);
            #pragma unroll
            for (int nd = 0; nd < 4; ++nd)
                #pragma unroll
                for (int o = 0; o < 2; ++o)
                    mma_bf16(oacc[nd * 2 + o], pal[0], pal[1], pal[2], pal[3], vh[nd][o], vh[nd][o + 2]);
        }
        __syncthreads();
    }

    float inv0 = 1.f / l[0], inv1 = 1.f / l[1];
    long row0 = (long)(b * Sq_ + q0 + warp * 16 + (lane >> 2));
    long row1 = row0 + 8;
    #pragma unroll
    for (int nf = 0; nf < 8; nf++) {
        int col = h * DHq_ + nf * 8 + (lane & 3) * 2;
        float v0 = oacc[nf][0] * inv0, v1 = oacc[nf][1] * inv0;
        float v2 = oacc[nf][2] * inv1, v3 = oacc[nf][3] * inv1;
        bf16 h0, l0, h1, l1, h2, l2, h3, l3;
        split2(v0, h0, l0); split2(v1, h1, l1);
        split2(v2, h2, l2); split2(v3, h3, l3);
        *(__nv_bfloat162*)&Ohi[row0 * Dq_ + col] = __nv_bfloat162(h0, h1);
        *(__nv_bfloat162*)&Olo[row0 * Dq_ + col] = __nv_bfloat162(l0, l1);
        *(__nv_bfloat162*)&Ohi[row1 * Dq_ + col] = __nv_bfloat162(h2, h3);
        *(__nv_bfloat162*)&Olo[row1 * Dq_ + col] = __nv_bfloat162(l2, l3);
    }
}

// ---------------- launcher ----------------
extern "C" void kernel_launch(void* const* d_in, const int* in_sizes, int n_in,
                              void* d_out, int out_size) {
    const int*   x    = (const int*)  d_in[0];
    const float* tok  = (const float*)d_in[1];
    const float* pos  = (const float*)d_in[2];
    const float* Wq   = (const float*)d_in[3];
    const float* bq   = (const float*)d_in[4];
    const float* Wk   = (const float*)d_in[5];
    const float* bk   = (const float*)d_in[6];
    const float* Wv   = (const float*)d_in[7];
    const float* bv   = (const float*)d_in[8];
    const float* Wo   = (const float*)d_in[9];
    const float* bo   = (const float*)d_in[10];
    const float* ln1w = (const float*)d_in[11];
    const float* ln1b = (const float*)d_in[12];
    const float* ln2w = (const float*)d_in[13];
    const float* ln2b = (const float*)d_in[14];
    const float* W1   = (const float*)d_in[15];
    const float* b1   = (const float*)d_in[16];
    const float* W2   = (const float*)d_in[17];
    const float* b2   = (const float*)d_in[18];
    const float* lnfw = (const float*)d_in[19];
    const float* lnfb = (const float*)d_in[20];
    const float* Wout = (const float*)d_in[21];
    const float* bout = (const float*)d_in[22];
    float* out = (float*)d_out;

    float *h;
    bf16 *ahi, *alo, *qhi, *qlo, *khi, *klo, *vhi, *vlo, *ohi, *olo, *fhi, *flo, *whi, *wlo;
    cudaGetSymbolAddress((void**)&h, g_h);
    cudaGetSymbolAddress((void**)&ahi, g_ahi);
    cudaGetSymbolAddress((void**)&alo, g_alo);
    cudaGetSymbolAddress((void**)&qhi, g_qhi);
    cudaGetSymbolAddress((void**)&qlo, g_qlo);
    cudaGetSymbolAddress((void**)&khi, g_khi);
    cudaGetSymbolAddress((void**)&klo, g_klo);
    cudaGetSymbolAddress((void**)&vhi, g_vhi);
    cudaGetSymbolAddress((void**)&vlo, g_vlo);
    cudaGetSymbolAddress((void**)&ohi, g_ohi);
    cudaGetSymbolAddress((void**)&olo, g_olo);
    cudaGetSymbolAddress((void**)&fhi, g_fhi);
    cudaGetSymbolAddress((void**)&flo, g_flo);
    cudaGetSymbolAddress((void**)&whi, g_whi);
    cudaGetSymbolAddress((void**)&wlo, g_wlo);

    cudaFuncSetAttribute((const void*)gemm_kernel<0,false>, cudaFuncAttributeMaxDynamicSharedMemorySize, GEMM_SMEM);
    cudaFuncSetAttribute((const void*)gemm_kernel<0,true>,  cudaFuncAttributeMaxDynamicSharedMemorySize, GEMM_SMEM);
    cudaFuncSetAttribute((const void*)gemm_kernel<1,false>, cudaFuncAttributeMaxDynamicSharedMemorySize, GEMM_SMEM);
    cudaFuncSetAttribute((const void*)gemm_kernel<2,false>, cudaFuncAttributeMaxDynamicSharedMemorySize, GEMM_SMEM);
    cudaFuncSetAttribute((const void*)gemm_qkv_kernel, cudaFuncAttributeMaxDynamicSharedMemorySize, GEMM_SMEM);
    cudaFuncSetAttribute((const void*)attn_kernel, cudaFuncAttributeMaxDynamicSharedMemorySize, ATTN_SMEM);

    // ---- weight prep (batched) ----
    dim3 tb(32, 8);
    tsplit_sq_kernel<<<dim3(24, 24, 48), tb>>>(Wq, Wk, Wv, Wo, whi, wlo);
    tsplit_w1_kernel<<<dim3(Hq_ / 32, 24, 12), tb>>>(W1, whi, wlo);
    tsplit_w2_kernel<<<dim3(24, Hq_ / 32, 12), tb>>>(W2, whi, wlo);
    tsplit_out_kernel<<<dim3(VPAD_ / 32, 24), tb>>>(Wout, whi, wlo);

    embed_kernel<<<Mq_, 256>>>(x, tok, pos, h);

    dim3 gD(Dq_ / 128, Mq_ / 128);
    dim3 gH(Hq_ / 128, Mq_ / 128);
    dim3 gVsw(Mq_ / 128, VPAD_ / 128);
    dim3 gQKV(Dq_ / 128, Mq_ / 128, 3);
    dim3 gAtt(Sq_ / 64, NHq_, Bq_);

    for (int i = 0; i < Lq_; ++i) {
        size_t off = (size_t)i * LWBLK;
        ln_kernel<<<Mq_, 256>>>(h, ln1w + i * Dq_, ln1b + i * Dq_, ahi, alo);
        gemm_qkv_kernel<<<gQKV, 256, GEMM_SMEM>>>(ahi, alo, whi + off, wlo + off,
            bq + i * Dq_, bk + i * Dq_, bv + i * Dq_,
            qhi, qlo, khi, klo, vhi, vlo);
        attn_kernel<<<gAtt, 128, ATTN_SMEM>>>(qhi, qlo, khi, klo, vhi, vlo, ohi, olo);
        gemm_kernel<2,false><<<gD, 256, GEMM_SMEM>>>(ohi, olo, whi + off + 3 * WSQ, wlo + off + 3 * WSQ,
            bo + i * Dq_, h, nullptr, nullptr, Dq_, Dq_, Dq_);
        ln_kernel<<<Mq_, 256>>>(h, ln2w + i * Dq_, ln2b + i * Dq_, ahi, alo);
        gemm_kernel<1,false><<<gH, 256, GEMM_SMEM>>>(ahi, alo, whi + off + 4 * WSQ, wlo + off + 4 * WSQ,
            b1 + i * Hq_, nullptr, fhi, flo, Dq_, Hq_, Hq_);
        gemm_kernel<2,false><<<gD, 256, GEMM_SMEM>>>(fhi, flo, whi + off + 4 * WSQ + WSH, wlo + off + 4 * WSQ + WSH,
            b2 + i * Dq_, h, nullptr, nullptr, Hq_, Dq_, Dq_);
    }

    ln_kernel<<<Mq_, 256>>>(h, lnfw, lnfb, ahi, alo);
    gemm_kernel<0,true><<<gVsw, 256, GEMM_SMEM>>>(ahi, alo, whi + WOUT_OFF, wlo + WOUT_OFF,
        bout, out, nullptr, nullptr, Dq_, VPAD_, Vq_);
}

// round 8
// speedup vs baseline: 1.6427x; 1.6273x over previous
#include <cuda_runtime.h>
#include <cuda_fp16.h>
#include <math.h>
#include <stdint.h>

// ---------------- problem constants ----------------
#define Bq_ 4
#define Sq_ 1024
#define Vq_ 50257
#define VPAD_ 50304
#define Dq_ 768
#define Hq_ 3072
#define NHq_ 12
#define DHq_ 64
#define Lq_ 12
#define Mq_ (Bq_*Sq_)   // 4096 rows

typedef __half f16;

#define WSQ (768UL*768UL)
#define WSH (768UL*3072UL)
#define LWBLK (4UL*WSQ + 2UL*WSH)
#define WOUT_OFF (LWBLK*12UL)
#define WTOT (WOUT_OFF + (size_t)VPAD_*Dq_)

// ---------------- scratch (device globals; no allocs allowed) ----------------
__device__ float g_h[Mq_*Dq_];
__device__ f16 g_a[Mq_*Dq_];
__device__ f16 g_q[Mq_*Dq_];
__device__ f16 g_k[Mq_*Dq_];
__device__ f16 g_v[Mq_*Dq_];
__device__ f16 g_o[Mq_*Dq_];
__device__ f16 g_f[Mq_*Hq_];
__device__ f16 g_whi[WTOT], g_wlo[WTOT];

// ---------------- helpers ----------------
__device__ __forceinline__ uint32_t s2u(const void* p) {
    return (uint32_t)__cvta_generic_to_shared(p);
}
__device__ __forceinline__ void cp16(uint32_t d, const void* s) {
    asm volatile("cp.async.cg.shared.global [%0], [%1], 16;\n" :: "r"(d), "l"(s) : "memory");
}
#define CP_COMMIT asm volatile("cp.async.commit_group;\n" ::: "memory")
#define CP_WAIT1  asm volatile("cp.async.wait_group 1;\n" ::: "memory")
#define CP_WAIT0  asm volatile("cp.async.wait_group 0;\n" ::: "memory")

__device__ __forceinline__ void ldsm4(uint32_t &r0, uint32_t &r1, uint32_t &r2, uint32_t &r3,
                                      uint32_t addr) {
    asm volatile("ldmatrix.sync.aligned.m8n8.x4.shared.b16 {%0,%1,%2,%3}, [%4];\n"
        : "=r"(r0), "=r"(r1), "=r"(r2), "=r"(r3) : "r"(addr));
}
__device__ __forceinline__ void ldsm4t(uint32_t &r0, uint32_t &r1, uint32_t &r2, uint32_t &r3,
                                       uint32_t addr) {
    asm volatile("ldmatrix.sync.aligned.m8n8.x4.trans.shared.b16 {%0,%1,%2,%3}, [%4];\n"
        : "=r"(r0), "=r"(r1), "=r"(r2), "=r"(r3) : "r"(addr));
}
__device__ __forceinline__ void mma_f16(float* c, uint32_t a0, uint32_t a1, uint32_t a2, uint32_t a3,
                                        uint32_t b0, uint32_t b1) {
    asm volatile("mma.sync.aligned.m16n8k16.row.col.f32.f16.f16.f32 "
        "{%0,%1,%2,%3},{%4,%5,%6,%7},{%8,%9},{%0,%1,%2,%3};\n"
        : "+f"(c[0]), "+f"(c[1]), "+f"(c[2]), "+f"(c[3])
        : "r"(a0), "r"(a1), "r"(a2), "r"(a3), "r"(b0), "r"(b1));
}
__device__ __forceinline__ void split2h(float x, f16& h, f16& l) {
    h = __float2half_rn(x);
    l = __float2half_rn(x - __half2float(h));
}
__device__ __forceinline__ uint32_t packh2(float a, float b) {
    __half2 t = __floats2half2_rn(a, b);
    return *(uint32_t*)&t;
}

// ---------------- weight transpose + split (batched) ----------------
__device__ __forceinline__ void tsplit_body(const float* __restrict__ W, f16* __restrict__ hi,
                                            f16* __restrict__ lo, int K, int Nsrc) {
    __shared__ float tile[32][33];
    int k0 = blockIdx.y * 32, n0 = blockIdx.x * 32;
    int tx = threadIdx.x, ty = threadIdx.y;
    #pragma unroll
    for (int i = 0; i < 4; i++) {
        int k = k0 + ty + i * 8, n = n0 + tx;
        tile[ty + i * 8][tx] = (n < Nsrc) ? W[(long)k * Nsrc + n] : 0.f;
    }
    __syncthreads();
    #pragma unroll
    for (int i = 0; i < 4; i++) {
        int n = n0 + ty + i * 8, k = k0 + tx;
        float v = tile[tx][ty + i * 8];
        f16 h, l; split2h(v, h, l);
        hi[(long)n * K + k] = h;
        lo[(long)n * K + k] = l;
    }
}

__global__ void tsplit_sq_kernel(const float* __restrict__ Wq, const float* __restrict__ Wk,
                                 const float* __restrict__ Wv, const float* __restrict__ Wo,
                                 f16* __restrict__ hi, f16* __restrict__ lo) {
    int z = blockIdx.z, layer = z >> 2, which = z & 3;
    const float* W = (which == 0 ? Wq : which == 1 ? Wk : which == 2 ? Wv : Wo) + (size_t)layer * WSQ;
    size_t off = (size_t)layer * LWBLK + (size_t)which * WSQ;
    tsplit_body(W, hi + off, lo + off, 768, 768);
}
__global__ void tsplit_w1_kernel(const float* __restrict__ W1, f16* __restrict__ hi, f16* __restrict__ lo) {
    int layer = blockIdx.z;
    size_t off = (size_t)layer * LWBLK + 4 * WSQ;
    tsplit_body(W1 + (size_t)layer * WSH, hi + off, lo + off, 768, Hq_);
}
__global__ void tsplit_w2_kernel(const float* __restrict__ W2, f16* __restrict__ hi, f16* __restrict__ lo) {
    int layer = blockIdx.z;
    size_t off = (size_t)layer * LWBLK + 4 * WSQ + WSH;
    tsplit_body(W2 + (size_t)layer * WSH, hi + off, lo + off, Hq_, 768);
}
__global__ void tsplit_out_kernel(const float* __restrict__ W, f16* __restrict__ hi, f16* __restrict__ lo) {
    tsplit_body(W, hi + WOUT_OFF, lo + WOUT_OFF, 768, Vq_);
}

// ---------------- embedding ----------------
__global__ void embed_kernel(const int* __restrict__ x,
                             const float* __restrict__ tok,
                             const float* __restrict__ pos,
                             float* __restrict__ h) {
    int row = blockIdx.x;
    int s = row & (Sq_ - 1);
    int tid = x[row];
    const float* tp = tok + (long)tid * Dq_;
    const float* pp = pos + (long)s * Dq_;
    float* hp = h + (long)row * Dq_;
    for (int d = threadIdx.x; d < Dq_; d += 256)
        hp[d] = tp[d] + pp[d];
}

// ---------------- layernorm -> single fp16 output ----------------
__global__ void ln_kernel(const float* __restrict__ X,
                          const float* __restrict__ w,
                          const float* __restrict__ bb,
                          f16* __restrict__ Y) {
    int row = blockIdx.x;
    const float* x = X + (long)row * Dq_;
    int t = threadIdx.x;
    float v0 = x[t], v1 = x[t + 256], v2 = x[t + 512];

    __shared__ float red[8];
    __shared__ float mean_s, inv_s;

    float s = v0 + v1 + v2;
    #pragma unroll
    for (int o = 16; o > 0; o >>= 1) s += __shfl_down_sync(0xffffffffu, s, o);
    if ((t & 31) == 0) red[t >> 5] = s;
    __syncthreads();
    if (t == 0) {
        float tot = 0.f;
        #pragma unroll
        for (int i = 0; i < 8; i++) tot += red[i];
        mean_s = tot * (1.0f / Dq_);
    }
    __syncthreads();
    float mean = mean_s;
    float d0 = v0 - mean, d1 = v1 - mean, d2 = v2 - mean;
    float q = d0 * d0 + d1 * d1 + d2 * d2;
    #pragma unroll
    for (int o = 16; o > 0; o >>= 1) q += __shfl_down_sync(0xffffffffu, q, o);
    if ((t & 31) == 0) red[t >> 5] = q;
    __syncthreads();
    if (t == 0) {
        float tot = 0.f;
        #pragma unroll
        for (int i = 0; i < 8; i++) tot += red[i];
        inv_s = rsqrtf(tot * (1.0f / Dq_) + 1e-5f);
    }
    __syncthreads();
    float inv = inv_s;
    long base = (long)row * Dq_;
    #pragma unroll
    for (int i = 0; i < 3; i++) {
        int c = t + i * 256;
        float dd = (i == 0 ? d0 : i == 1 ? d1 : d2);
        Y[base + c] = __float2half_rn(dd * inv * w[c] + bb[c]);
    }
}

// ---------------- fp16 2-term HMMA GEMM, 3-stage pipeline ----------------
// C = A[MxK](f16) * (Bh+Bl)^T (B stored [N][K] hi/lo f16) + bias
// EPI: 0 = fp32 C; 1 = GELU -> f16; 2 = fp32 residual add in-place; 3 = f16 out
// smem: [3 buf][3 arr: A,Bh,Bl][128][40]
#define GEMM_SMEM (3 * 3 * 128 * 40 * 2)   // 92160

template<int EPI, bool SWAP>
__device__ __forceinline__ void gemm_body(
    const f16* __restrict__ A,
    const f16* __restrict__ Bhi, const f16* __restrict__ Blo,
    const float* __restrict__ bias,
    float* __restrict__ C, f16* __restrict__ C16,
    int K, int N, int Nout)
{
    extern __shared__ f16 sm[];
    uint32_t smb = s2u(sm);
    int tid = threadIdx.x;
    int bm = (SWAP ? blockIdx.x : blockIdx.y) * 128;
    int bn = (SWAP ? blockIdx.y : blockIdx.x) * 128;
    int warp = tid >> 5, lane = tid & 31;
    int wm = warp >> 2, wn = warp & 3;

    float acc[4][4][4];
    #pragma unroll
    for (int i = 0; i < 4; i++)
        #pragma unroll
        for (int j = 0; j < 4; j++)
            #pragma unroll
            for (int k = 0; k < 4; k++) acc[i][j][k] = 0.f;

    const f16* srcs[3] = { A + (long)bm * K, Bhi + (long)bn * K, Blo + (long)bn * K };

    auto issue = [&](int b, int kt) {
        int k0 = kt * 32;
        #pragma unroll
        for (int arr = 0; arr < 3; arr++) {
            #pragma unroll
            for (int i = 0; i < 2; i++) {
                int ch = tid + i * 256;
                int row = ch >> 2, cg = ch & 3;
                uint32_t dst = smb + ((((b * 3 + arr) * 128 + row) * 40) + cg * 8) * 2;
                cp16(dst, srcs[arr] + (long)row * K + k0 + cg * 8);
            }
        }
    };

    int nk = K >> 5;
    issue(0, 0); CP_COMMIT;
    issue(1, 1); CP_COMMIT;

    int lrow = lane & 15, lcg = lane >> 4;

    for (int kt = 0; kt < nk; ++kt) {
        int cur = kt % 3;
        if (kt + 1 < nk) { CP_WAIT1; } else { CP_WAIT0; }
        __syncthreads();
        if (kt + 2 < nk) { issue((kt + 2) % 3, kt + 2); CP_COMMIT; }

        #pragma unroll
        for (int ks = 0; ks < 2; ++ks) {
            uint32_t af[4][4];
            #pragma unroll
            for (int mf = 0; mf < 4; mf++) {
                int row = wm * 64 + mf * 16 + lrow;
                int col = ks * 16 + lcg * 8;
                uint32_t a0 = smb + ((((cur * 3 + 0) * 128 + row) * 40) + col) * 2;
                ldsm4(af[mf][0], af[mf][1], af[mf][2], af[mf][3], a0);
            }
            uint32_t bh[2][4], bl[2][4];
            #pragma unroll
            for (int nf2 = 0; nf2 < 2; nf2++) {
                int row = wn * 32 + nf2 * 16 + lrow;
                int col = ks * 16 + lcg * 8;
                uint32_t b0 = smb + ((((cur * 3 + 1) * 128 + row) * 40) + col) * 2;
                uint32_t b1 = smb + ((((cur * 3 + 2) * 128 + row) * 40) + col) * 2;
                ldsm4(bh[nf2][0], bh[nf2][1], bh[nf2][2], bh[nf2][3], b0);
                ldsm4(bl[nf2][0], bl[nf2][1], bl[nf2][2], bl[nf2][3], b1);
            }
            #pragma unroll
            for (int mf = 0; mf < 4; mf++)
                #pragma unroll
                for (int nf = 0; nf < 4; nf++) {
                    int g = nf >> 1, o = nf & 1;
                    mma_f16(acc[mf][nf], af[mf][0], af[mf][1], af[mf][2], af[mf][3],
                            bh[g][o], bh[g][o + 2]);
                }
            #pragma unroll
            for (int mf = 0; mf < 4; mf++)
                #pragma unroll
                for (int nf = 0; nf < 4; nf++) {
                    int g = nf >> 1, o = nf & 1;
                    mma_f16(acc[mf][nf], af[mf][0], af[mf][1], af[mf][2], af[mf][3],
                            bl[g][o], bl[g][o + 2]);
                }
        }
    }

    int r = lane >> 2, c2 = (lane & 3) * 2;
    #pragma unroll
    for (int mf = 0; mf < 4; mf++) {
        #pragma unroll
        for (int nf = 0; nf < 4; nf++) {
            #pragma unroll
            for (int half2_ = 0; half2_ < 2; half2_++) {
                long row = bm + wm * 64 + mf * 16 + r + half2_ * 8;
                #pragma unroll
                for (int e = 0; e < 2; e++) {
                    int col = bn + wn * 32 + nf * 8 + c2 + e;
                    if (col < Nout) {
                        float v = acc[mf][nf][half2_ * 2 + e] + bias[col];
                        if (EPI == 1 || EPI == 3) {
                            if (EPI == 1)
                                v = 0.5f * v * (1.f + erff(v * 0.70710678118654752f));
                            C16[row * N + col] = __float2half_rn(v);
                        } else if (EPI == 2) {
                            v += C[row * (long)Nout + col];
                            C[row * (long)Nout + col] = v;
                        } else {
                            C[row * (long)Nout + col] = v;
                        }
                    }
                }
            }
        }
    }
}

template<int EPI, bool SWAP>
__global__ __launch_bounds__(256, 1) void gemm_kernel(
    const f16* __restrict__ A,
    const f16* __restrict__ Bhi, const f16* __restrict__ Blo,
    const float* __restrict__ bias,
    float* __restrict__ C, f16* __restrict__ C16,
    int K, int N, int Nout)
{
    gemm_body<EPI, SWAP>(A, Bhi, Blo, bias, C, C16, K, N, Nout);
}

__global__ __launch_bounds__(256, 1) void gemm_qkv_kernel(
    const f16* __restrict__ A,
    const f16* __restrict__ whi, const f16* __restrict__ wlo,
    const float* __restrict__ bq, const float* __restrict__ bk, const float* __restrict__ bv,
    f16* __restrict__ q, f16* __restrict__ k, f16* __restrict__ v)
{
    int z = blockIdx.z;
    const f16* Bh = whi + (size_t)z * WSQ;
    const f16* Bl = wlo + (size_t)z * WSQ;
    const float* bias = (z == 0) ? bq : (z == 1) ? bk : bv;
    f16* C16 = (z == 0) ? q : (z == 1) ? k : v;
    gemm_body<3, false>(A, Bh, Bl, bias, nullptr, C16, Dq_, Dq_, Dq_);
}

// ---------------- HMMA flash attention, single fp16 ----------------
#define AT_STRIDE 72
#define AT_TILE (64 * AT_STRIDE)
#define ATTN_SMEM (3 * AT_TILE * 2)   // 27648

__global__ __launch_bounds__(128, 4) void attn_kernel(
    const f16* __restrict__ Qg, const f16* __restrict__ Kg, const f16* __restrict__ Vg,
    f16* __restrict__ O)
{
    extern __shared__ f16 asm_[];
    uint32_t smb = s2u(asm_);
    uint32_t sQ = smb;
    uint32_t sK = sQ + AT_TILE * 2;
    uint32_t sV = sK + AT_TILE * 2;

    int t = threadIdx.x, warp = t >> 5, lane = t & 31;
    int q0 = blockIdx.x * 64, h = blockIdx.y, b = blockIdx.z;

    long rowbase = (long)(b * Sq_ + q0) * Dq_ + h * DHq_;

    #pragma unroll
    for (int i = 0; i < 4; i++) {
        int idx = t + i * 128;
        int row = idx >> 3, ch = idx & 7;
        uint32_t doff = (uint32_t)(row * AT_STRIDE + ch * 8) * 2;
        cp16(sQ + doff, Qg + rowbase + (long)row * Dq_ + ch * 8);
    }

    float m[2] = { -1e30f, -1e30f }, l[2] = { 0.f, 0.f };
    float oacc[8][4];
    #pragma unroll
    for (int i = 0; i < 8; i++)
        #pragma unroll
        for (int j = 0; j < 4; j++) oacc[i][j] = 0.f;

    int lrow = lane & 15, lcg = lane >> 4;

    for (int j0 = 0; j0 <= q0; j0 += 64) {
        long kbase = (long)(b * Sq_ + j0) * Dq_ + h * DHq_;
        #pragma unroll
        for (int i = 0; i < 4; i++) {
            int idx = t + i * 128;
            int row = idx >> 3, ch = idx & 7;
            uint32_t doff = (uint32_t)(row * AT_STRIDE + ch * 8) * 2;
            long goff = kbase + (long)row * Dq_ + ch * 8;
            cp16(sK + doff, Kg + goff);
            cp16(sV + doff, Vg + goff);
        }
        CP_COMMIT; CP_WAIT0;
        __syncthreads();

        float sacc[8][4];
        #pragma unroll
        for (int i = 0; i < 8; i++)
            #pragma unroll
            for (int j = 0; j < 4; j++) sacc[i][j] = 0.f;

        #pragma unroll
        for (int ks = 0; ks < 4; ++ks) {
            int acol = ks * 16 + lcg * 8;
            uint32_t qf[4];
            uint32_t qaddr = (uint32_t)((warp * 16 + lrow) * AT_STRIDE + acol) * 2;
            ldsm4(qf[0], qf[1], qf[2], qf[3], sQ + qaddr);
            uint32_t kf[4][4];
            #pragma unroll
            for (int kg = 0; kg < 4; ++kg) {
                uint32_t kaddr = (uint32_t)((kg * 16 + lrow) * AT_STRIDE + acol) * 2;
                ldsm4(kf[kg][0], kf[kg][1], kf[kg][2], kf[kg][3], sK + kaddr);
            }
            #pragma unroll
            for (int kg = 0; kg < 4; ++kg)
                #pragma unroll
                for (int o = 0; o < 2; ++o)
                    mma_f16(sacc[kg * 2 + o], qf[0], qf[1], qf[2], qf[3], kf[kg][o], kf[kg][o + 2]);
        }

        int r0loc = warp * 16 + (lane >> 2);
        bool diag = (j0 == q0);
        float mx[2] = { -1e30f, -1e30f };
        #pragma unroll
        for (int nf = 0; nf < 8; nf++) {
            #pragma unroll
            for (int i = 0; i < 4; i++) {
                float v = sacc[nf][i] * 0.125f;
                if (diag) {
                    int col = nf * 8 + (lane & 3) * 2 + (i & 1);
                    int row = r0loc + ((i >> 1) ? 8 : 0);
                    if (col > row) v = -1e30f;
                }
                sacc[nf][i] = v;
                mx[i >> 1] = fmaxf(mx[i >> 1], v);
            }
        }
        #pragma unroll
        for (int o = 1; o < 4; o <<= 1) {
            mx[0] = fmaxf(mx[0], __shfl_xor_sync(0xffffffffu, mx[0], o));
            mx[1] = fmaxf(mx[1], __shfl_xor_sync(0xffffffffu, mx[1], o));
        }
        float fac[2], sum[2] = { 0.f, 0.f };
        #pragma unroll
        for (int j = 0; j < 2; j++) {
            float mnew = fmaxf(m[j], mx[j]);
            fac[j] = __expf(m[j] - mnew);
            m[j] = mnew;
        }
        #pragma unroll
        for (int nf = 0; nf < 8; nf++) {
            #pragma unroll
            for (int i = 0; i < 4; i++) {
                float p = __expf(sacc[nf][i] - m[i >> 1]);
                sacc[nf][i] = p;
                sum[i >> 1] += p;
            }
        }
        #pragma unroll
        for (int o = 1; o < 4; o <<= 1) {
            sum[0] += __shfl_xor_sync(0xffffffffu, sum[0], o);
            sum[1] += __shfl_xor_sync(0xffffffffu, sum[1], o);
        }
        #pragma unroll
        for (int j = 0; j < 2; j++) l[j] = l[j] * fac[j] + sum[j];
        #pragma unroll
        for (int nf = 0; nf < 8; nf++) {
            oacc[nf][0] *= fac[0]; oacc[nf][1] *= fac[0];
            oacc[nf][2] *= fac[1]; oacc[nf][3] *= fac[1];
        }

        #pragma unroll
        for (int t2 = 0; t2 < 4; ++t2) {
            float* p0 = sacc[2 * t2];
            float* p1 = sacc[2 * t2 + 1];
            uint32_t pa[4];
            pa[0] = packh2(p0[0], p0[1]);
            pa[1] = packh2(p0[2], p0[3]);
            pa[2] = packh2(p1[0], p1[1]);
            pa[3] = packh2(p1[2], p1[3]);

            uint32_t vf[4][4];
            #pragma unroll
            for (int nd = 0; nd < 4; ++nd) {
                uint32_t vrow = (uint32_t)(t2 * 16 + ((lane >> 4) << 3) + (lane & 7));
                uint32_t vcol = (uint32_t)(nd * 16 + (((lane >> 3) & 1) << 3));
                uint32_t vaddr = (vrow * AT_STRIDE + vcol) * 2;
                ldsm4t(vf[nd][0], vf[nd][1], vf[nd][2], vf[nd][3], sV + vaddr);
            }
            #pragma unroll
            for (int nd = 0; nd < 4; ++nd)
                #pragma unroll
                for (int o = 0; o < 2; ++o)
                    mma_f16(oacc[nd * 2 + o], pa[0], pa[1], pa[2], pa[3], vf[nd][o], vf[nd][o + 2]);
        }
        __syncthreads();
    }

    float inv0 = 1.f / l[0], inv1 = 1.f / l[1];
    long row0 = (long)(b * Sq_ + q0 + warp * 16 + (lane >> 2));
    long row1 = row0 + 8;
    #pragma unroll
    for (int nf = 0; nf < 8; nf++) {
        int col = h * DHq_ + nf * 8 + (lane & 3) * 2;
        *(__half2*)&O[row0 * Dq_ + col] = __floats2half2_rn(oacc[nf][0] * inv0, oacc[nf][1] * inv0);
        *(__half2*)&O[row1 * Dq_ + col] = __floats2half2_rn(oacc[nf][2] * inv1, oacc[nf][3] * inv1);
    }
}

// ---------------- launcher ----------------
extern "C" void kernel_launch(void* const* d_in, const int* in_sizes, int n_in,
                              void* d_out, int out_size) {
    const int*   x    = (const int*)  d_in[0];
    const float* tok  = (const float*)d_in[1];
    const float* pos  = (const float*)d_in[2];
    const float* Wq   = (const float*)d_in[3];
    const float* bq   = (const float*)d_in[4];
    const float* Wk   = (const float*)d_in[5];
    const float* bk   = (const float*)d_in[6];
    const float* Wv   = (const float*)d_in[7];
    const float* bv   = (const float*)d_in[8];
    const float* Wo   = (const float*)d_in[9];
    const float* bo   = (const float*)d_in[10];
    const float* ln1w = (const float*)d_in[11];
    const float* ln1b = (const float*)d_in[12];
    const float* ln2w = (const float*)d_in[13];
    const float* ln2b = (const float*)d_in[14];
    const float* W1   = (const float*)d_in[15];
    const float* b1   = (const float*)d_in[16];
    const float* W2   = (const float*)d_in[17];
    const float* b2   = (const float*)d_in[18];
    const float* lnfw = (const float*)d_in[19];
    const float* lnfb = (const float*)d_in[20];
    const float* Wout = (const float*)d_in[21];
    const float* bout = (const float*)d_in[22];
    float* out = (float*)d_out;

    float *h;
    f16 *a, *q, *k, *v, *o, *f, *whi, *wlo;
    cudaGetSymbolAddress((void**)&h, g_h);
    cudaGetSymbolAddress((void**)&a, g_a);
    cudaGetSymbolAddress((void**)&q, g_q);
    cudaGetSymbolAddress((void**)&k, g_k);
    cudaGetSymbolAddress((void**)&v, g_v);
    cudaGetSymbolAddress((void**)&o, g_o);
    cudaGetSymbolAddress((void**)&f, g_f);
    cudaGetSymbolAddress((void**)&whi, g_whi);
    cudaGetSymbolAddress((void**)&wlo, g_wlo);

    cudaFuncSetAttribute((const void*)gemm_kernel<0,false>, cudaFuncAttributeMaxDynamicSharedMemorySize, GEMM_SMEM);
    cudaFuncSetAttribute((const void*)gemm_kernel<0,true>,  cudaFuncAttributeMaxDynamicSharedMemorySize, GEMM_SMEM);
    cudaFuncSetAttribute((const void*)gemm_kernel<1,false>, cudaFuncAttributeMaxDynamicSharedMemorySize, GEMM_SMEM);
    cudaFuncSetAttribute((const void*)gemm_kernel<2,false>, cudaFuncAttributeMaxDynamicSharedMemorySize, GEMM_SMEM);
    cudaFuncSetAttribute((const void*)gemm_qkv_kernel, cudaFuncAttributeMaxDynamicSharedMemorySize, GEMM_SMEM);
    cudaFuncSetAttribute((const void*)attn_kernel, cudaFuncAttributeMaxDynamicSharedMemorySize, ATTN_SMEM);

    // ---- weight prep (batched) ----
    dim3 tb(32, 8);
    tsplit_sq_kernel<<<dim3(24, 24, 48), tb>>>(Wq, Wk, Wv, Wo, whi, wlo);
    tsplit_w1_kernel<<<dim3(Hq_ / 32, 24, 12), tb>>>(W1, whi, wlo);
    tsplit_w2_kernel<<<dim3(24, Hq_ / 32, 12), tb>>>(W2, whi, wlo);
    tsplit_out_kernel<<<dim3(VPAD_ / 32, 24), tb>>>(Wout, whi, wlo);

    embed_kernel<<<Mq_, 256>>>(x, tok, pos, h);

    dim3 gD(Dq_ / 128, Mq_ / 128);
    dim3 gH(Hq_ / 128, Mq_ / 128);
    dim3 gVsw(Mq_ / 128, VPAD_ / 128);
    dim3 gQKV(Dq_ / 128, Mq_ / 128, 3);
    dim3 gAtt(Sq_ / 64, NHq_, Bq_);

    for (int i = 0; i < Lq_; ++i) {
        size_t off = (size_t)i * LWBLK;
        ln_kernel<<<Mq_, 256>>>(h, ln1w + i * Dq_, ln1b + i * Dq_, a);
        gemm_qkv_kernel<<<gQKV, 256, GEMM_SMEM>>>(a, whi + off, wlo + off,
            bq + i * Dq_, bk + i * Dq_, bv + i * Dq_, q, k, v);
        attn_kernel<<<gAtt, 128, ATTN_SMEM>>>(q, k, v, o);
        gemm_kernel<2,false><<<gD, 256, GEMM_SMEM>>>(o, whi + off + 3 * WSQ, wlo + off + 3 * WSQ,
            bo + i * Dq_, h, nullptr, Dq_, Dq_, Dq_);
        ln_kernel<<<Mq_, 256>>>(h, ln2w + i * Dq_, ln2b + i * Dq_, a);
        gemm_kernel<1,false><<<gH, 256, GEMM_SMEM>>>(a, whi + off + 4 * WSQ, wlo + off + 4 * WSQ,
            b1 + i * Hq_, nullptr, f, Dq_, Hq_, Hq_);
        gemm_kernel<2,false><<<gD, 256, GEMM_SMEM>>>(f, whi + off + 4 * WSQ + WSH, wlo + off + 4 * WSQ + WSH,
            b2 + i * Dq_, h, nullptr, Hq_, Dq_, Dq_);
    }

    ln_kernel<<<Mq_, 256>>>(h, lnfw, lnfb, a);
    gemm_kernel<0,true><<<gVsw, 256, GEMM_SMEM>>>(a, whi + WOUT_OFF, wlo + WOUT_OFF,
        bout, out, nullptr, Dq_, VPAD_, Vq_);
}

// round 9
// speedup vs baseline: 1.7968x; 1.0938x over previous
#include <cuda_runtime.h>
#include <cuda_fp16.h>
#include <math.h>
#include <stdint.h>

// ---------------- problem constants ----------------
#define Bq_ 4
#define Sq_ 1024
#define Vq_ 50257
#define VPAD_ 50304
#define Dq_ 768
#define Hq_ 3072
#define NHq_ 12
#define DHq_ 64
#define Lq_ 12
#define Mq_ (Bq_*Sq_)   // 4096 rows

typedef __half f16;

#define WSQ (768UL*768UL)
#define WSH (768UL*3072UL)
#define LWBLK (4UL*WSQ + 2UL*WSH)
#define WOUT_OFF (LWBLK*12UL)
#define WTOT (WOUT_OFF + (size_t)VPAD_*Dq_)

// ---------------- scratch (device globals; no allocs allowed) ----------------
__device__ float g_h[Mq_*Dq_];
__device__ f16 g_a[Mq_*Dq_];
__device__ f16 g_q[Mq_*Dq_];
__device__ f16 g_k[Mq_*Dq_];
__device__ f16 g_v[Mq_*Dq_];
__device__ f16 g_o[Mq_*Dq_];
__device__ f16 g_f[Mq_*Hq_];
__device__ f16 g_whi[WTOT], g_wlo[WTOT];   // wlo unused beyond layer blocks for Wout

// ---------------- helpers ----------------
__device__ __forceinline__ uint32_t s2u(const void* p) {
    return (uint32_t)__cvta_generic_to_shared(p);
}
__device__ __forceinline__ void cp16(uint32_t d, const void* s) {
    asm volatile("cp.async.cg.shared.global [%0], [%1], 16;\n" :: "r"(d), "l"(s) : "memory");
}
#define CP_COMMIT asm volatile("cp.async.commit_group;\n" ::: "memory")
#define CP_WAIT1  asm volatile("cp.async.wait_group 1;\n" ::: "memory")
#define CP_WAIT0  asm volatile("cp.async.wait_group 0;\n" ::: "memory")

__device__ __forceinline__ void ldsm4(uint32_t &r0, uint32_t &r1, uint32_t &r2, uint32_t &r3,
                                      uint32_t addr) {
    asm volatile("ldmatrix.sync.aligned.m8n8.x4.shared.b16 {%0,%1,%2,%3}, [%4];\n"
        : "=r"(r0), "=r"(r1), "=r"(r2), "=r"(r3) : "r"(addr));
}
__device__ __forceinline__ void ldsm4t(uint32_t &r0, uint32_t &r1, uint32_t &r2, uint32_t &r3,
                                       uint32_t addr) {
    asm volatile("ldmatrix.sync.aligned.m8n8.x4.trans.shared.b16 {%0,%1,%2,%3}, [%4];\n"
        : "=r"(r0), "=r"(r1), "=r"(r2), "=r"(r3) : "r"(addr));
}
__device__ __forceinline__ void mma_f16(float* c, uint32_t a0, uint32_t a1, uint32_t a2, uint32_t a3,
                                        uint32_t b0, uint32_t b1) {
    asm volatile("mma.sync.aligned.m16n8k16.row.col.f32.f16.f16.f32 "
        "{%0,%1,%2,%3},{%4,%5,%6,%7},{%8,%9},{%0,%1,%2,%3};\n"
        : "+f"(c[0]), "+f"(c[1]), "+f"(c[2]), "+f"(c[3])
        : "r"(a0), "r"(a1), "r"(a2), "r"(a3), "r"(b0), "r"(b1));
}
__device__ __forceinline__ void split2h(float x, f16& h, f16& l) {
    h = __float2half_rn(x);
    l = __float2half_rn(x - __half2float(h));
}
__device__ __forceinline__ uint32_t packh2(float a, float b) {
    __half2 t = __floats2half2_rn(a, b);
    return *(uint32_t*)&t;
}

// ---------------- weight transpose + split (batched) ----------------
template<bool WRITE_LO>
__device__ __forceinline__ void tsplit_body(const float* __restrict__ W, f16* __restrict__ hi,
                                            f16* __restrict__ lo, int K, int Nsrc) {
    __shared__ float tile[32][33];
    int k0 = blockIdx.y * 32, n0 = blockIdx.x * 32;
    int tx = threadIdx.x, ty = threadIdx.y;
    #pragma unroll
    for (int i = 0; i < 4; i++) {
        int k = k0 + ty + i * 8, n = n0 + tx;
        tile[ty + i * 8][tx] = (n < Nsrc) ? W[(long)k * Nsrc + n] : 0.f;
    }
    __syncthreads();
    #pragma unroll
    for (int i = 0; i < 4; i++) {
        int n = n0 + ty + i * 8, k = k0 + tx;
        float v = tile[tx][ty + i * 8];
        f16 h, l; split2h(v, h, l);
        hi[(long)n * K + k] = h;
        if (WRITE_LO) lo[(long)n * K + k] = l;
    }
}

__global__ void tsplit_sq_kernel(const float* __restrict__ Wq, const float* __restrict__ Wk,
                                 const float* __restrict__ Wv, const float* __restrict__ Wo,
                                 f16* __restrict__ hi, f16* __restrict__ lo) {
    int z = blockIdx.z, layer = z >> 2, which = z & 3;
    const float* W = (which == 0 ? Wq : which == 1 ? Wk : which == 2 ? Wv : Wo) + (size_t)layer * WSQ;
    size_t off = (size_t)layer * LWBLK + (size_t)which * WSQ;
    tsplit_body<true>(W, hi + off, lo + off, 768, 768);
}
__global__ void tsplit_w1_kernel(const float* __restrict__ W1, f16* __restrict__ hi, f16* __restrict__ lo) {
    int layer = blockIdx.z;
    size_t off = (size_t)layer * LWBLK + 4 * WSQ;
    tsplit_body<true>(W1 + (size_t)layer * WSH, hi + off, lo + off, 768, Hq_);
}
__global__ void tsplit_w2_kernel(const float* __restrict__ W2, f16* __restrict__ hi, f16* __restrict__ lo) {
    int layer = blockIdx.z;
    size_t off = (size_t)layer * LWBLK + 4 * WSQ + WSH;
    tsplit_body<true>(W2 + (size_t)layer * WSH, hi + off, lo + off, Hq_, 768);
}
__global__ void tsplit_out_kernel(const float* __restrict__ W, f16* __restrict__ hi) {
    tsplit_body<false>(W, hi + WOUT_OFF, nullptr, 768, Vq_);   // single-term logits: hi only
}

// ---------------- embedding ----------------
__global__ void embed_kernel(const int* __restrict__ x,
                             const float* __restrict__ tok,
                             const float* __restrict__ pos,
                             float* __restrict__ h) {
    int row = blockIdx.x;
    int s = row & (Sq_ - 1);
    int tid = x[row];
    const float* tp = tok + (long)tid * Dq_;
    const float* pp = pos + (long)s * Dq_;
    float* hp = h + (long)row * Dq_;
    for (int d = threadIdx.x; d < Dq_; d += 256)
        hp[d] = tp[d] + pp[d];
}

// ---------------- layernorm -> single fp16 output ----------------
__global__ void ln_kernel(const float* __restrict__ X,
                          const float* __restrict__ w,
                          const float* __restrict__ bb,
                          f16* __restrict__ Y) {
    int row = blockIdx.x;
    const float* x = X + (long)row * Dq_;
    int t = threadIdx.x;
    float v0 = x[t], v1 = x[t + 256], v2 = x[t + 512];

    __shared__ float red[8];
    __shared__ float mean_s, inv_s;

    float s = v0 + v1 + v2;
    #pragma unroll
    for (int o = 16; o > 0; o >>= 1) s += __shfl_down_sync(0xffffffffu, s, o);
    if ((t & 31) == 0) red[t >> 5] = s;
    __syncthreads();
    if (t == 0) {
        float tot = 0.f;
        #pragma unroll
        for (int i = 0; i < 8; i++) tot += red[i];
        mean_s = tot * (1.0f / Dq_);
    }
    __syncthreads();
    float mean = mean_s;
    float d0 = v0 - mean, d1 = v1 - mean, d2 = v2 - mean;
    float q = d0 * d0 + d1 * d1 + d2 * d2;
    #pragma unroll
    for (int o = 16; o > 0; o >>= 1) q += __shfl_down_sync(0xffffffffu, q, o);
    if ((t & 31) == 0) red[t >> 5] = q;
    __syncthreads();
    if (t == 0) {
        float tot = 0.f;
        #pragma unroll
        for (int i = 0; i < 8; i++) tot += red[i];
        inv_s = rsqrtf(tot * (1.0f / Dq_) + 1e-5f);
    }
    __syncthreads();
    float inv = inv_s;
    long base = (long)row * Dq_;
    #pragma unroll
    for (int i = 0; i < 3; i++) {
        int c = t + i * 256;
        float dd = (i == 0 ? d0 : i == 1 ? d1 : d2);
        Y[base + c] = __float2half_rn(dd * inv * w[c] + bb[c]);
    }
}

// ---------------- fp16 HMMA GEMM, 3-stage pipeline, 1- or 2-term B ----------------
// C = A[MxK](f16) * (Bh [+ Bl])^T + bias
// EPI: 0 = fp32 C; 1 = GELU -> f16; 2 = fp32 residual add in-place; 3 = f16 out
// smem: [3 buf][1+NTERMS arr][128][40]
#define GEMM_SMEM (3 * 3 * 128 * 40 * 2)   // 92160 (max; NTERMS=1 uses less)

template<int EPI, bool SWAP, int NTERMS>
__device__ __forceinline__ void gemm_body(
    const f16* __restrict__ A,
    const f16* __restrict__ Bhi, const f16* __restrict__ Blo,
    const float* __restrict__ bias,
    float* __restrict__ C, f16* __restrict__ C16,
    int K, int N, int Nout)
{
    const int ARR = 1 + NTERMS;
    extern __shared__ f16 sm[];
    uint32_t smb = s2u(sm);
    int tid = threadIdx.x;
    int bm = (SWAP ? blockIdx.x : blockIdx.y) * 128;
    int bn = (SWAP ? blockIdx.y : blockIdx.x) * 128;
    int warp = tid >> 5, lane = tid & 31;
    int wm = warp >> 2, wn = warp & 3;

    float acc[4][4][4];
    #pragma unroll
    for (int i = 0; i < 4; i++)
        #pragma unroll
        for (int j = 0; j < 4; j++)
            #pragma unroll
            for (int k = 0; k < 4; k++) acc[i][j][k] = 0.f;

    const f16* srcs[3] = { A + (long)bm * K, Bhi + (long)bn * K,
                           (NTERMS == 2) ? Blo + (long)bn * K : nullptr };

    auto issue = [&](int b, int kt) {
        int k0 = kt * 32;
        #pragma unroll
        for (int arr = 0; arr < ARR; arr++) {
            #pragma unroll
            for (int i = 0; i < 2; i++) {
                int ch = tid + i * 256;
                int row = ch >> 2, cg = ch & 3;
                uint32_t dst = smb + ((((b * ARR + arr) * 128 + row) * 40) + cg * 8) * 2;
                cp16(dst, srcs[arr] + (long)row * K + k0 + cg * 8);
            }
        }
    };

    int nk = K >> 5;
    issue(0, 0); CP_COMMIT;
    issue(1, 1); CP_COMMIT;

    int lrow = lane & 15, lcg = lane >> 4;

    for (int kt = 0; kt < nk; ++kt) {
        int cur = kt % 3;
        if (kt + 1 < nk) { CP_WAIT1; } else { CP_WAIT0; }
        __syncthreads();
        if (kt + 2 < nk) { issue((kt + 2) % 3, kt + 2); CP_COMMIT; }

        #pragma unroll
        for (int ks = 0; ks < 2; ++ks) {
            uint32_t af[4][4];
            #pragma unroll
            for (int mf = 0; mf < 4; mf++) {
                int row = wm * 64 + mf * 16 + lrow;
                int col = ks * 16 + lcg * 8;
                uint32_t a0 = smb + ((((cur * ARR + 0) * 128 + row) * 40) + col) * 2;
                ldsm4(af[mf][0], af[mf][1], af[mf][2], af[mf][3], a0);
            }
            uint32_t bh[2][4], bl[2][4];
            #pragma unroll
            for (int nf2 = 0; nf2 < 2; nf2++) {
                int row = wn * 32 + nf2 * 16 + lrow;
                int col = ks * 16 + lcg * 8;
                uint32_t b0 = smb + ((((cur * ARR + 1) * 128 + row) * 40) + col) * 2;
                ldsm4(bh[nf2][0], bh[nf2][1], bh[nf2][2], bh[nf2][3], b0);
                if (NTERMS == 2) {
                    uint32_t b1 = smb + ((((cur * ARR + 2) * 128 + row) * 40) + col) * 2;
                    ldsm4(bl[nf2][0], bl[nf2][1], bl[nf2][2], bl[nf2][3], b1);
                }
            }
            #pragma unroll
            for (int mf = 0; mf < 4; mf++)
                #pragma unroll
                for (int nf = 0; nf < 4; nf++) {
                    int g = nf >> 1, o = nf & 1;
                    mma_f16(acc[mf][nf], af[mf][0], af[mf][1], af[mf][2], af[mf][3],
                            bh[g][o], bh[g][o + 2]);
                }
            if (NTERMS == 2) {
                #pragma unroll
                for (int mf = 0; mf < 4; mf++)
                    #pragma unroll
                    for (int nf = 0; nf < 4; nf++) {
                        int g = nf >> 1, o = nf & 1;
                        mma_f16(acc[mf][nf], af[mf][0], af[mf][1], af[mf][2], af[mf][3],
                                bl[g][o], bl[g][o + 2]);
                    }
            }
        }
    }

    int r = lane >> 2, c2 = (lane & 3) * 2;
    #pragma unroll
    for (int mf = 0; mf < 4; mf++) {
        #pragma unroll
        for (int nf = 0; nf < 4; nf++) {
            #pragma unroll
            for (int half2_ = 0; half2_ < 2; half2_++) {
                long row = bm + wm * 64 + mf * 16 + r + half2_ * 8;
                #pragma unroll
                for (int e = 0; e < 2; e++) {
                    int col = bn + wn * 32 + nf * 8 + c2 + e;
                    if (col < Nout) {
                        float v = acc[mf][nf][half2_ * 2 + e] + bias[col];
                        if (EPI == 1 || EPI == 3) {
                            if (EPI == 1)
                                v = 0.5f * v * (1.f + erff(v * 0.70710678118654752f));
                            C16[row * N + col] = __float2half_rn(v);
                        } else if (EPI == 2) {
                            v += C[row * (long)Nout + col];
                            C[row * (long)Nout + col] = v;
                        } else {
                            C[row * (long)Nout + col] = v;
                        }
                    }
                }
            }
        }
    }
}

template<int EPI, bool SWAP, int NTERMS>
__global__ __launch_bounds__(256, 1) void gemm_kernel(
    const f16* __restrict__ A,
    const f16* __restrict__ Bhi, const f16* __restrict__ Blo,
    const float* __restrict__ bias,
    float* __restrict__ C, f16* __restrict__ C16,
    int K, int N, int Nout)
{
    gemm_body<EPI, SWAP, NTERMS>(A, Bhi, Blo, bias, C, C16, K, N, Nout);
}

__global__ __launch_bounds__(256, 1) void gemm_qkv_kernel(
    const f16* __restrict__ A,
    const f16* __restrict__ whi, const f16* __restrict__ wlo,
    const float* __restrict__ bq, const float* __restrict__ bk, const float* __restrict__ bv,
    f16* __restrict__ q, f16* __restrict__ k, f16* __restrict__ v)
{
    int z = blockIdx.z;
    const f16* Bh = whi + (size_t)z * WSQ;
    const f16* Bl = wlo + (size_t)z * WSQ;
    const float* bias = (z == 0) ? bq : (z == 1) ? bk : bv;
    f16* C16 = (z == 0) ? q : (z == 1) ? k : v;
    gemm_body<3, false, 2>(A, Bh, Bl, bias, nullptr, C16, Dq_, Dq_, Dq_);
}

// ---------------- HMMA flash attention, single fp16 ----------------
#define AT_STRIDE 72
#define AT_TILE (64 * AT_STRIDE)
#define ATTN_SMEM (3 * AT_TILE * 2)   // 27648

__global__ __launch_bounds__(128, 4) void attn_kernel(
    const f16* __restrict__ Qg, const f16* __restrict__ Kg, const f16* __restrict__ Vg,
    f16* __restrict__ O)
{
    extern __shared__ f16 asm_[];
    uint32_t smb = s2u(asm_);
    uint32_t sQ = smb;
    uint32_t sK = sQ + AT_TILE * 2;
    uint32_t sV = sK + AT_TILE * 2;

    int t = threadIdx.x, warp = t >> 5, lane = t & 31;
    int q0 = blockIdx.x * 64, h = blockIdx.y, b = blockIdx.z;

    long rowbase = (long)(b * Sq_ + q0) * Dq_ + h * DHq_;

    #pragma unroll
    for (int i = 0; i < 4; i++) {
        int idx = t + i * 128;
        int row = idx >> 3, ch = idx & 7;
        uint32_t doff = (uint32_t)(row * AT_STRIDE + ch * 8) * 2;
        cp16(sQ + doff, Qg + rowbase + (long)row * Dq_ + ch * 8);
    }

    float m[2] = { -1e30f, -1e30f }, l[2] = { 0.f, 0.f };
    float oacc[8][4];
    #pragma unroll
    for (int i = 0; i < 8; i++)
        #pragma unroll
        for (int j = 0; j < 4; j++) oacc[i][j] = 0.f;

    int lrow = lane & 15, lcg = lane >> 4;

    for (int j0 = 0; j0 <= q0; j0 += 64) {
        long kbase = (long)(b * Sq_ + j0) * Dq_ + h * DHq_;
        #pragma unroll
        for (int i = 0; i < 4; i++) {
            int idx = t + i * 128;
            int row = idx >> 3, ch = idx & 7;
            uint32_t doff = (uint32_t)(row * AT_STRIDE + ch * 8) * 2;
            long goff = kbase + (long)row * Dq_ + ch * 8;
            cp16(sK + doff, Kg + goff);
            cp16(sV + doff, Vg + goff);
        }
        CP_COMMIT; CP_WAIT0;
        __syncthreads();

        float sacc[8][4];
        #pragma unroll
        for (int i = 0; i < 8; i++)
            #pragma unroll
            for (int j = 0; j < 4; j++) sacc[i][j] = 0.f;

        #pragma unroll
        for (int ks = 0; ks < 4; ++ks) {
            int acol = ks * 16 + lcg * 8;
            uint32_t qf[4];
            uint32_t qaddr = (uint32_t)((warp * 16 + lrow) * AT_STRIDE + acol) * 2;
            ldsm4(qf[0], qf[1], qf[2], qf[3], sQ + qaddr);
            uint32_t kf[4][4];
            #pragma unroll
            for (int kg = 0; kg < 4; ++kg) {
                uint32_t kaddr = (uint32_t)((kg * 16 + lrow) * AT_STRIDE + acol) * 2;
                ldsm4(kf[kg][0], kf[kg][1], kf[kg][2], kf[kg][3], sK + kaddr);
            }
            #pragma unroll
            for (int kg = 0; kg < 4; ++kg)
                #pragma unroll
                for (int o = 0; o < 2; ++o)
                    mma_f16(sacc[kg * 2 + o], qf[0], qf[1], qf[2], qf[3], kf[kg][o], kf[kg][o + 2]);
        }

        int r0loc = warp * 16 + (lane >> 2);
        bool diag = (j0 == q0);
        float mx[2] = { -1e30f, -1e30f };
        #pragma unroll
        for (int nf = 0; nf < 8; nf++) {
            #pragma unroll
            for (int i = 0; i < 4; i++) {
                float v = sacc[nf][i] * 0.125f;
                if (diag) {
                    int col = nf * 8 + (lane & 3) * 2 + (i & 1);
                    int row = r0loc + ((i >> 1) ? 8 : 0);
                    if (col > row) v = -1e30f;
                }
                sacc[nf][i] = v;
                mx[i >> 1] = fmaxf(mx[i >> 1], v);
            }
        }
        #pragma unroll
        for (int o = 1; o < 4; o <<= 1) {
            mx[0] = fmaxf(mx[0], __shfl_xor_sync(0xffffffffu, mx[0], o));
            mx[1] = fmaxf(mx[1], __shfl_xor_sync(0xffffffffu, mx[1], o));
        }
        float fac[2], sum[2] = { 0.f, 0.f };
        #pragma unroll
        for (int j = 0; j < 2; j++) {
            float mnew = fmaxf(m[j], mx[j]);
            fac[j] = __expf(m[j] - mnew);
            m[j] = mnew;
        }
        #pragma unroll
        for (int nf = 0; nf < 8; nf++) {
            #pragma unroll
            for (int i = 0; i < 4; i++) {
                float p = __expf(sacc[nf][i] - m[i >> 1]);
                sacc[nf][i] = p;
                sum[i >> 1] += p;
            }
        }
        #pragma unroll
        for (int o = 1; o < 4; o <<= 1) {
            sum[0] += __shfl_xor_sync(0xffffffffu, sum[0], o);
            sum[1] += __shfl_xor_sync(0xffffffffu, sum[1], o);
        }
        #pragma unroll
        for (int j = 0; j < 2; j++) l[j] = l[j] * fac[j] + sum[j];
        #pragma unroll
        for (int nf = 0; nf < 8; nf++) {
            oacc[nf][0] *= fac[0]; oacc[nf][1] *= fac[0];
            oacc[nf][2] *= fac[1]; oacc[nf][3] *= fac[1];
        }

        #pragma unroll
        for (int t2 = 0; t2 < 4; ++t2) {
            float* p0 = sacc[2 * t2];
            float* p1 = sacc[2 * t2 + 1];
            uint32_t pa[4];
            pa[0] = packh2(p0[0], p0[1]);
            pa[1] = packh2(p0[2], p0[3]);
            pa[2] = packh2(p1[0], p1[1]);
            pa[3] = packh2(p1[2], p1[3]);

            uint32_t vf[4][4];
            #pragma unroll
            for (int nd = 0; nd < 4; ++nd) {
                uint32_t vrow = (uint32_t)(t2 * 16 + ((lane >> 4) << 3) + (lane & 7));
                uint32_t vcol = (uint32_t)(nd * 16 + (((lane >> 3) & 1) << 3));
                uint32_t vaddr = (vrow * AT_STRIDE + vcol) * 2;
                ldsm4t(vf[nd][0], vf[nd][1], vf[nd][2], vf[nd][3], sV + vaddr);
            }
            #pragma unroll
            for (int nd = 0; nd < 4; ++nd)
                #pragma unroll
                for (int o = 0; o < 2; ++o)
                    mma_f16(oacc[nd * 2 + o], pa[0], pa[1], pa[2], pa[3], vf[nd][o], vf[nd][o + 2]);
        }
        __syncthreads();
    }

    float inv0 = 1.f / l[0], inv1 = 1.f / l[1];
    long row0 = (long)(b * Sq_ + q0 + warp * 16 + (lane >> 2));
    long row1 = row0 + 8;
    #pragma unroll
    for (int nf = 0; nf < 8; nf++) {
        int col = h * DHq_ + nf * 8 + (lane & 3) * 2;
        *(__half2*)&O[row0 * Dq_ + col] = __floats2half2_rn(oacc[nf][0] * inv0, oacc[nf][1] * inv0);
        *(__half2*)&O[row1 * Dq_ + col] = __floats2half2_rn(oacc[nf][2] * inv1, oacc[nf][3] * inv1);
    }
}

// ---------------- launcher ----------------
extern "C" void kernel_launch(void* const* d_in, const int* in_sizes, int n_in,
                              void* d_out, int out_size) {
    const int*   x    = (const int*)  d_in[0];
    const float* tok  = (const float*)d_in[1];
    const float* pos  = (const float*)d_in[2];
    const float* Wq   = (const float*)d_in[3];
    const float* bq   = (const float*)d_in[4];
    const float* Wk   = (const float*)d_in[5];
    const float* bk   = (const float*)d_in[6];
    const float* Wv   = (const float*)d_in[7];
    const float* bv   = (const float*)d_in[8];
    const float* Wo   = (const float*)d_in[9];
    const float* bo   = (const float*)d_in[10];
    const float* ln1w = (const float*)d_in[11];
    const float* ln1b = (const float*)d_in[12];
    const float* ln2w = (const float*)d_in[13];
    const float* ln2b = (const float*)d_in[14];
    const float* W1   = (const float*)d_in[15];
    const float* b1   = (const float*)d_in[16];
    const float* W2   = (const float*)d_in[17];
    const float* b2   = (const float*)d_in[18];
    const float* lnfw = (const float*)d_in[19];
    const float* lnfb = (const float*)d_in[20];
    const float* Wout = (const float*)d_in[21];
    const float* bout = (const float*)d_in[22];
    float* out = (float*)d_out;

    float *h;
    f16 *a, *q, *k, *v, *o, *f, *whi, *wlo;
    cudaGetSymbolAddress((void**)&h, g_h);
    cudaGetSymbolAddress((void**)&a, g_a);
    cudaGetSymbolAddress((void**)&q, g_q);
    cudaGetSymbolAddress((void**)&k, g_k);
    cudaGetSymbolAddress((void**)&v, g_v);
    cudaGetSymbolAddress((void**)&o, g_o);
    cudaGetSymbolAddress((void**)&f, g_f);
    cudaGetSymbolAddress((void**)&whi, g_whi);
    cudaGetSymbolAddress((void**)&wlo, g_wlo);

    cudaFuncSetAttribute((const void*)gemm_kernel<0,true,1>,  cudaFuncAttributeMaxDynamicSharedMemorySize, GEMM_SMEM);
    cudaFuncSetAttribute((const void*)gemm_kernel<1,false,2>, cudaFuncAttributeMaxDynamicSharedMemorySize, GEMM_SMEM);
    cudaFuncSetAttribute((const void*)gemm_kernel<2,false,2>, cudaFuncAttributeMaxDynamicSharedMemorySize, GEMM_SMEM);
    cudaFuncSetAttribute((const void*)gemm_qkv_kernel, cudaFuncAttributeMaxDynamicSharedMemorySize, GEMM_SMEM);
    cudaFuncSetAttribute((const void*)attn_kernel, cudaFuncAttributeMaxDynamicSharedMemorySize, ATTN_SMEM);

    // ---- weight prep (batched) ----
    dim3 tb(32, 8);
    tsplit_sq_kernel<<<dim3(24, 24, 48), tb>>>(Wq, Wk, Wv, Wo, whi, wlo);
    tsplit_w1_kernel<<<dim3(Hq_ / 32, 24, 12), tb>>>(W1, whi, wlo);
    tsplit_w2_kernel<<<dim3(24, Hq_ / 32, 12), tb>>>(W2, whi, wlo);
    tsplit_out_kernel<<<dim3(VPAD_ / 32, 24), tb>>>(Wout, whi);

    embed_kernel<<<Mq_, 256>>>(x, tok, pos, h);

    dim3 gD(Dq_ / 128, Mq_ / 128);
    dim3 gH(Hq_ / 128, Mq_ / 128);
    dim3 gVsw(Mq_ / 128, VPAD_ / 128);
    dim3 gQKV(Dq_ / 128, Mq_ / 128, 3);
    dim3 gAtt(Sq_ / 64, NHq_, Bq_);

    for (int i = 0; i < Lq_; ++i) {
        size_t off = (size_t)i * LWBLK;
        ln_kernel<<<Mq_, 256>>>(h, ln1w + i * Dq_, ln1b + i * Dq_, a);
        gemm_qkv_kernel<<<gQKV, 256, GEMM_SMEM>>>(a, whi + off, wlo + off,
            bq + i * Dq_, bk + i * Dq_, bv + i * Dq_, q, k, v);
        attn_kernel<<<gAtt, 128, ATTN_SMEM>>>(q, k, v, o);
        gemm_kernel<2,false,2><<<gD, 256, GEMM_SMEM>>>(o, whi + off + 3 * WSQ, wlo + off + 3 * WSQ,
            bo + i * Dq_, h, nullptr, Dq_, Dq_, Dq_);
        ln_kernel<<<Mq_, 256>>>(h, ln2w + i * Dq_, ln2b + i * Dq_, a);
        gemm_kernel<1,false,2><<<gH, 256, GEMM_SMEM>>>(a, whi + off + 4 * WSQ, wlo + off + 4 * WSQ,
            b1 + i * Hq_, nullptr, f, Dq_, Hq_, Hq_);
        gemm_kernel<2,false,2><<<gD, 256, GEMM_SMEM>>>(f, whi + off + 4 * WSQ + WSH, wlo + off + 4 * WSQ + WSH,
            b2 + i * Dq_, h, nullptr, Hq_, Dq_, Dq_);
    }

    ln_kernel<<<Mq_, 256>>>(h, lnfw, lnfb, a);
    gemm_kernel<0,true,1><<<gVsw, 256, GEMM_SMEM>>>(a, whi + WOUT_OFF, nullptr,
        bout, out, nullptr, Dq_, VPAD_, Vq_);
}

// round 10
// speedup vs baseline: 1.9359x; 1.0774x over previous
#include <cuda_runtime.h>
#include <cuda_fp16.h>
#include <math.h>
#include <stdint.h>

// ---------------- problem constants ----------------
#define Bq_ 4
#define Sq_ 1024
#define Vq_ 50257
#define VPAD_ 50304
#define Dq_ 768
#define Hq_ 3072
#define NHq_ 12
#define DHq_ 64
#define Lq_ 12
#define Mq_ (Bq_*Sq_)   // 4096 rows

typedef __half f16;

#define WSQ (768UL*768UL)
#define WSH (768UL*3072UL)
#define LWBLK (4UL*WSQ + 2UL*WSH)
#define WOUT_OFF (LWBLK*12UL)
#define WTOT (WOUT_OFF + (size_t)VPAD_*Dq_)

// ---------------- scratch (device globals; no allocs allowed) ----------------
__device__ float g_h[Mq_*Dq_];
__device__ float g_p[2UL*Mq_*Dq_];          // split-K partial planes
__device__ f16 g_a[Mq_*Dq_];
__device__ f16 g_q[Mq_*Dq_];
__device__ f16 g_k[Mq_*Dq_];
__device__ f16 g_v[Mq_*Dq_];
__device__ f16 g_o[Mq_*Dq_];
__device__ f16 g_f[Mq_*Hq_];
__device__ f16 g_whi[WTOT], g_wlo[WTOT];

// ---------------- helpers ----------------
__device__ __forceinline__ uint32_t s2u(const void* p) {
    return (uint32_t)__cvta_generic_to_shared(p);
}
__device__ __forceinline__ void cp16(uint32_t d, const void* s) {
    asm volatile("cp.async.cg.shared.global [%0], [%1], 16;\n" :: "r"(d), "l"(s) : "memory");
}
#define CP_COMMIT asm volatile("cp.async.commit_group;\n" ::: "memory")
#define CP_WAIT1  asm volatile("cp.async.wait_group 1;\n" ::: "memory")
#define CP_WAIT0  asm volatile("cp.async.wait_group 0;\n" ::: "memory")

__device__ __forceinline__ void ldsm4(uint32_t &r0, uint32_t &r1, uint32_t &r2, uint32_t &r3,
                                      uint32_t addr) {
    asm volatile("ldmatrix.sync.aligned.m8n8.x4.shared.b16 {%0,%1,%2,%3}, [%4];\n"
        : "=r"(r0), "=r"(r1), "=r"(r2), "=r"(r3) : "r"(addr));
}
__device__ __forceinline__ void ldsm4t(uint32_t &r0, uint32_t &r1, uint32_t &r2, uint32_t &r3,
                                       uint32_t addr) {
    asm volatile("ldmatrix.sync.aligned.m8n8.x4.trans.shared.b16 {%0,%1,%2,%3}, [%4];\n"
        : "=r"(r0), "=r"(r1), "=r"(r2), "=r"(r3) : "r"(addr));
}
__device__ __forceinline__ void mma_f16(float* c, uint32_t a0, uint32_t a1, uint32_t a2, uint32_t a3,
                                        uint32_t b0, uint32_t b1) {
    asm volatile("mma.sync.aligned.m16n8k16.row.col.f32.f16.f16.f32 "
        "{%0,%1,%2,%3},{%4,%5,%6,%7},{%8,%9},{%0,%1,%2,%3};\n"
        : "+f"(c[0]), "+f"(c[1]), "+f"(c[2]), "+f"(c[3])
        : "r"(a0), "r"(a1), "r"(a2), "r"(a3), "r"(b0), "r"(b1));
}
__device__ __forceinline__ void split2h(float x, f16& h, f16& l) {
    h = __float2half_rn(x);
    l = __float2half_rn(x - __half2float(h));
}
__device__ __forceinline__ uint32_t packh2(float a, float b) {
    __half2 t = __floats2half2_rn(a, b);
    return *(uint32_t*)&t;
}

// ---------------- weight transpose + split (batched) ----------------
template<bool WRITE_LO>
__device__ __forceinline__ void tsplit_body(const float* __restrict__ W, f16* __restrict__ hi,
                                            f16* __restrict__ lo, int K, int Nsrc) {
    __shared__ float tile[32][33];
    int k0 = blockIdx.y * 32, n0 = blockIdx.x * 32;
    int tx = threadIdx.x, ty = threadIdx.y;
    #pragma unroll
    for (int i = 0; i < 4; i++) {
        int k = k0 + ty + i * 8, n = n0 + tx;
        tile[ty + i * 8][tx] = (n < Nsrc) ? W[(long)k * Nsrc + n] : 0.f;
    }
    __syncthreads();
    #pragma unroll
    for (int i = 0; i < 4; i++) {
        int n = n0 + ty + i * 8, k = k0 + tx;
        float v = tile[tx][ty + i * 8];
        f16 h, l; split2h(v, h, l);
        hi[(long)n * K + k] = h;
        if (WRITE_LO) lo[(long)n * K + k] = l;
    }
}

__global__ void tsplit_sq_kernel(const float* __restrict__ Wq, const float* __restrict__ Wk,
                                 const float* __restrict__ Wv, const float* __restrict__ Wo,
                                 f16* __restrict__ hi, f16* __restrict__ lo) {
    int z = blockIdx.z, layer = z >> 2, which = z & 3;
    const float* W = (which == 0 ? Wq : which == 1 ? Wk : which == 2 ? Wv : Wo) + (size_t)layer * WSQ;
    size_t off = (size_t)layer * LWBLK + (size_t)which * WSQ;
    tsplit_body<true>(W, hi + off, lo + off, 768, 768);
}
__global__ void tsplit_w1_kernel(const float* __restrict__ W1, f16* __restrict__ hi, f16* __restrict__ lo) {
    int layer = blockIdx.z;
    size_t off = (size_t)layer * LWBLK + 4 * WSQ;
    tsplit_body<true>(W1 + (size_t)layer * WSH, hi + off, lo + off, 768, Hq_);
}
__global__ void tsplit_w2_kernel(const float* __restrict__ W2, f16* __restrict__ hi, f16* __restrict__ lo) {
    int layer = blockIdx.z;
    size_t off = (size_t)layer * LWBLK + 4 * WSQ + WSH;
    tsplit_body<true>(W2 + (size_t)layer * WSH, hi + off, lo + off, Hq_, 768);
}
__global__ void tsplit_out_kernel(const float* __restrict__ W, f16* __restrict__ hi) {
    tsplit_body<false>(W, hi + WOUT_OFF, nullptr, 768, Vq_);
}

// ---------------- embedding ----------------
__global__ void embed_kernel(const int* __restrict__ x,
                             const float* __restrict__ tok,
                             const float* __restrict__ pos,
                             float* __restrict__ h) {
    int row = blockIdx.x;
    int s = row & (Sq_ - 1);
    int tid = x[row];
    const float* tp = tok + (long)tid * Dq_;
    const float* pp = pos + (long)s * Dq_;
    float* hp = h + (long)row * Dq_;
    for (int d = threadIdx.x; d < Dq_; d += 256)
        hp[d] = tp[d] + pp[d];
}

// ---------------- layernorm (plain, first use) ----------------
__device__ __forceinline__ void ln_core(float v0, float v1, float v2,
                                        const float* __restrict__ w,
                                        const float* __restrict__ bb,
                                        f16* __restrict__ Y, long base, int t) {
    __shared__ float red[8];
    __shared__ float mean_s, inv_s;

    float s = v0 + v1 + v2;
    #pragma unroll
    for (int o = 16; o > 0; o >>= 1) s += __shfl_down_sync(0xffffffffu, s, o);
    if ((t & 31) == 0) red[t >> 5] = s;
    __syncthreads();
    if (t == 0) {
        float tot = 0.f;
        #pragma unroll
        for (int i = 0; i < 8; i++) tot += red[i];
        mean_s = tot * (1.0f / Dq_);
    }
    __syncthreads();
    float mean = mean_s;
    float d0 = v0 - mean, d1 = v1 - mean, d2 = v2 - mean;
    float q = d0 * d0 + d1 * d1 + d2 * d2;
    #pragma unroll
    for (int o = 16; o > 0; o >>= 1) q += __shfl_down_sync(0xffffffffu, q, o);
    if ((t & 31) == 0) red[t >> 5] = q;
    __syncthreads();
    if (t == 0) {
        float tot = 0.f;
        #pragma unroll
        for (int i = 0; i < 8; i++) tot += red[i];
        inv_s = rsqrtf(tot * (1.0f / Dq_) + 1e-5f);
    }
    __syncthreads();
    float inv = inv_s;
    Y[base + t]       = __float2half_rn(d0 * inv * w[t]       + bb[t]);
    Y[base + t + 256] = __float2half_rn(d1 * inv * w[t + 256] + bb[t + 256]);
    Y[base + t + 512] = __float2half_rn(d2 * inv * w[t + 512] + bb[t + 512]);
}

__global__ void ln_kernel(const float* __restrict__ X,
                          const float* __restrict__ w,
                          const float* __restrict__ bb,
                          f16* __restrict__ Y) {
    int row = blockIdx.x;
    const float* x = X + (long)row * Dq_;
    int t = threadIdx.x;
    ln_core(x[t], x[t + 256], x[t + 512], w, bb, Y, (long)row * Dq_, t);
}

// residual-sum + layernorm: h' = h + P0 + P1 (optional write-back), Y = LN(h')
template<bool WRITEH>
__global__ void ln_sum_kernel(float* __restrict__ H,
                              const float* __restrict__ P0, const float* __restrict__ P1,
                              const float* __restrict__ w, const float* __restrict__ bb,
                              f16* __restrict__ Y) {
    int row = blockIdx.x;
    long base = (long)row * Dq_;
    int t = threadIdx.x;
    float v0 = H[base + t]       + P0[base + t]       + P1[base + t];
    float v1 = H[base + t + 256] + P0[base + t + 256] + P1[base + t + 256];
    float v2 = H[base + t + 512] + P0[base + t + 512] + P1[base + t + 512];
    if (WRITEH) {
        H[base + t]       = v0;
        H[base + t + 256] = v1;
        H[base + t + 512] = v2;
    }
    ln_core(v0, v1, v2, w, bb, Y, base, t);
}

// ---------------- fp16 HMMA GEMM, 3-stage pipeline ----------------
// C = A[MxK](f16) * (Bh [+ Bl])^T + bias
// EPI: 0 = fp32 C+bias; 1 = GELU -> f16; 3 = f16 out; 4 = split-K fp32 partial plane
#define GEMM_SMEM (3 * 3 * 128 * 40 * 2)   // 92160 max

template<int EPI, bool SWAP, int NTERMS>
__device__ __forceinline__ void gemm_body(
    const f16* __restrict__ A,
    const f16* __restrict__ Bhi, const f16* __restrict__ Blo,
    const float* __restrict__ bias,
    float* __restrict__ C, f16* __restrict__ C16,
    int K, int N, int Nout)
{
    const int ARR = 1 + NTERMS;
    extern __shared__ f16 sm[];
    uint32_t smb = s2u(sm);
    int tid = threadIdx.x;
    int bm = (SWAP ? blockIdx.x : blockIdx.y) * 128;
    int bn = (SWAP ? blockIdx.y : blockIdx.x) * 128;
    int warp = tid >> 5, lane = tid & 31;
    int wm = warp >> 2, wn = warp & 3;

    int kz = (EPI == 4) ? blockIdx.z : 0;
    int Keff = (EPI == 4) ? (K >> 1) : K;
    long koff = (long)kz * Keff;

    float acc[4][4][4];
    #pragma unroll
    for (int i = 0; i < 4; i++)
        #pragma unroll
        for (int j = 0; j < 4; j++)
            #pragma unroll
            for (int k = 0; k < 4; k++) acc[i][j][k] = 0.f;

    const f16* srcs[3] = { A + (long)bm * K + koff, Bhi + (long)bn * K + koff,
                           (NTERMS == 2) ? Blo + (long)bn * K + koff : nullptr };

    auto issue = [&](int b, int kt) {
        int k0 = kt * 32;
        #pragma unroll
        for (int arr = 0; arr < ARR; arr++) {
            #pragma unroll
            for (int i = 0; i < 2; i++) {
                int ch = tid + i * 256;
                int row = ch >> 2, cg = ch & 3;
                uint32_t dst = smb + ((((b * ARR + arr) * 128 + row) * 40) + cg * 8) * 2;
                cp16(dst, srcs[arr] + (long)row * K + k0 + cg * 8);
            }
        }
    };

    int nk = Keff >> 5;
    issue(0, 0); CP_COMMIT;
    issue(1, 1); CP_COMMIT;

    int lrow = lane & 15, lcg = lane >> 4;

    for (int kt = 0; kt < nk; ++kt) {
        int cur = kt % 3;
        if (kt + 1 < nk) { CP_WAIT1; } else { CP_WAIT0; }
        __syncthreads();
        if (kt + 2 < nk) { issue((kt + 2) % 3, kt + 2); CP_COMMIT; }

        #pragma unroll
        for (int ks = 0; ks < 2; ++ks) {
            uint32_t af[4][4];
            #pragma unroll
            for (int mf = 0; mf < 4; mf++) {
                int row = wm * 64 + mf * 16 + lrow;
                int col = ks * 16 + lcg * 8;
                uint32_t a0 = smb + ((((cur * ARR + 0) * 128 + row) * 40) + col) * 2;
                ldsm4(af[mf][0], af[mf][1], af[mf][2], af[mf][3], a0);
            }
            uint32_t bh[2][4], bl[2][4];
            #pragma unroll
            for (int nf2 = 0; nf2 < 2; nf2++) {
                int row = wn * 32 + nf2 * 16 + lrow;
                int col = ks * 16 + lcg * 8;
                uint32_t b0 = smb + ((((cur * ARR + 1) * 128 + row) * 40) + col) * 2;
                ldsm4(bh[nf2][0], bh[nf2][1], bh[nf2][2], bh[nf2][3], b0);
                if (NTERMS == 2) {
                    uint32_t b1 = smb + ((((cur * ARR + 2) * 128 + row) * 40) + col) * 2;
                    ldsm4(bl[nf2][0], bl[nf2][1], bl[nf2][2], bl[nf2][3], b1);
                }
            }
            #pragma unroll
            for (int mf = 0; mf < 4; mf++)
                #pragma unroll
                for (int nf = 0; nf < 4; nf++) {
                    int g = nf >> 1, o = nf & 1;
                    mma_f16(acc[mf][nf], af[mf][0], af[mf][1], af[mf][2], af[mf][3],
                            bh[g][o], bh[g][o + 2]);
                }
            if (NTERMS == 2) {
                #pragma unroll
                for (int mf = 0; mf < 4; mf++)
                    #pragma unroll
                    for (int nf = 0; nf < 4; nf++) {
                        int g = nf >> 1, o = nf & 1;
                        mma_f16(acc[mf][nf], af[mf][0], af[mf][1], af[mf][2], af[mf][3],
                                bl[g][o], bl[g][o + 2]);
                    }
            }
        }
    }

    float* Cp = (EPI == 4) ? (C + (size_t)kz * Mq_ * (size_t)Nout) : C;

    int r = lane >> 2, c2 = (lane & 3) * 2;
    #pragma unroll
    for (int mf = 0; mf < 4; mf++) {
        #pragma unroll
        for (int nf = 0; nf < 4; nf++) {
            #pragma unroll
            for (int half2_ = 0; half2_ < 2; half2_++) {
                long row = bm + wm * 64 + mf * 16 + r + half2_ * 8;
                #pragma unroll
                for (int e = 0; e < 2; e++) {
                    int col = bn + wn * 32 + nf * 8 + c2 + e;
                    if (col < Nout) {
                        float v = acc[mf][nf][half2_ * 2 + e];
                        if (EPI == 4) {
                            if (kz == 0) v += bias[col];
                            Cp[row * (long)Nout + col] = v;
                        } else {
                            v += bias[col];
                            if (EPI == 1 || EPI == 3) {
                                if (EPI == 1)
                                    v = 0.5f * v * (1.f + erff(v * 0.70710678118654752f));
                                C16[row * N + col] = __float2half_rn(v);
                            } else {
                                Cp[row * (long)Nout + col] = v;
                            }
                        }
                    }
                }
            }
        }
    }
}

template<int EPI, bool SWAP, int NTERMS>
__global__ __launch_bounds__(256, 1) void gemm_kernel(
    const f16* __restrict__ A,
    const f16* __restrict__ Bhi, const f16* __restrict__ Blo,
    const float* __restrict__ bias,
    float* __restrict__ C, f16* __restrict__ C16,
    int K, int N, int Nout)
{
    gemm_body<EPI, SWAP, NTERMS>(A, Bhi, Blo, bias, C, C16, K, N, Nout);
}

__global__ __launch_bounds__(256, 1) void gemm_qkv_kernel(
    const f16* __restrict__ A,
    const f16* __restrict__ whi, const f16* __restrict__ wlo,
    const float* __restrict__ bq, const float* __restrict__ bk, const float* __restrict__ bv,
    f16* __restrict__ q, f16* __restrict__ k, f16* __restrict__ v)
{
    int z = blockIdx.z;
    const f16* Bh = whi + (size_t)z * WSQ;
    const f16* Bl = wlo + (size_t)z * WSQ;
    const float* bias = (z == 0) ? bq : (z == 1) ? bk : bv;
    f16* C16 = (z == 0) ? q : (z == 1) ? k : v;
    gemm_body<3, false, 2>(A, Bh, Bl, bias, nullptr, C16, Dq_, Dq_, Dq_);
}

// ---------------- HMMA flash attention, single fp16, double-buffered K/V ----------------
#define AT_STRIDE 72
#define AT_TILE (64 * AT_STRIDE)
#define ATTN_SMEM (5 * AT_TILE * 2)   // Q + 2x(K,V) = 46080

__global__ __launch_bounds__(128, 4) void attn_kernel(
    const f16* __restrict__ Qg, const f16* __restrict__ Kg, const f16* __restrict__ Vg,
    f16* __restrict__ O)
{
    extern __shared__ f16 asm_[];
    uint32_t smb = s2u(asm_);
    uint32_t sQ = smb;

    int t = threadIdx.x, warp = t >> 5, lane = t & 31;
    int q0 = blockIdx.x * 64, h = blockIdx.y, b = blockIdx.z;

    long rowbase = (long)(b * Sq_ + q0) * Dq_ + h * DHq_;

    auto issue_kv = [&](int buf, int jt) {
        uint32_t sK = smb + (1 + buf * 2) * AT_TILE * 2;
        uint32_t sV = sK + AT_TILE * 2;
        long kbase = (long)(b * Sq_ + jt * 64) * Dq_ + h * DHq_;
        #pragma unroll
        for (int i = 0; i < 4; i++) {
            int idx = t + i * 128;
            int row = idx >> 3, ch = idx & 7;
            uint32_t doff = (uint32_t)(row * AT_STRIDE + ch * 8) * 2;
            long goff = kbase + (long)row * Dq_ + ch * 8;
            cp16(sK + doff, Kg + goff);
            cp16(sV + doff, Vg + goff);
        }
    };

    // prologue: Q + first K/V tile in one group
    #pragma unroll
    for (int i = 0; i < 4; i++) {
        int idx = t + i * 128;
        int row = idx >> 3, ch = idx & 7;
        uint32_t doff = (uint32_t)(row * AT_STRIDE + ch * 8) * 2;
        cp16(sQ + doff, Qg + rowbase + (long)row * Dq_ + ch * 8);
    }
    issue_kv(0, 0);
    CP_COMMIT;

    float m[2] = { -1e30f, -1e30f }, l[2] = { 0.f, 0.f };
    float oacc[8][4];
    #pragma unroll
    for (int i = 0; i < 8; i++)
        #pragma unroll
        for (int j = 0; j < 4; j++) oacc[i][j] = 0.f;

    int lrow = lane & 15, lcg = lane >> 4;
    int ntiles = q0 / 64 + 1;

    for (int it = 0; it < ntiles; ++it) {
        if (it + 1 < ntiles) { issue_kv((it + 1) & 1, it + 1); CP_COMMIT; CP_WAIT1; }
        else                 { CP_WAIT0; }
        __syncthreads();

        uint32_t sK = smb + (1 + (it & 1) * 2) * AT_TILE * 2;
        uint32_t sV = sK + AT_TILE * 2;
        int j0 = it * 64;

        float sacc[8][4];
        #pragma unroll
        for (int i = 0; i < 8; i++)
            #pragma unroll
            for (int j = 0; j < 4; j++) sacc[i][j] = 0.f;

        #pragma unroll
        for (int ks = 0; ks < 4; ++ks) {
            int acol = ks * 16 + lcg * 8;
            uint32_t qf[4];
            uint32_t qaddr = (uint32_t)((warp * 16 + lrow) * AT_STRIDE + acol) * 2;
            ldsm4(qf[0], qf[1], qf[2], qf[3], sQ + qaddr);
            uint32_t kf[4][4];
            #pragma unroll
            for (int kg = 0; kg < 4; ++kg) {
                uint32_t kaddr = (uint32_t)((kg * 16 + lrow) * AT_STRIDE + acol) * 2;
                ldsm4(kf[kg][0], kf[kg][1], kf[kg][2], kf[kg][3], sK + kaddr);
            }
            #pragma unroll
            for (int kg = 0; kg < 4; ++kg)
                #pragma unroll
                for (int o = 0; o < 2; ++o)
                    mma_f16(sacc[kg * 2 + o], qf[0], qf[1], qf[2], qf[3], kf[kg][o], kf[kg][o + 2]);
        }

        int r0loc = warp * 16 + (lane >> 2);
        bool diag = (j0 == q0);
        float mx[2] = { -1e30f, -1e30f };
        #pragma unroll
        for (int nf = 0; nf < 8; nf++) {
            #pragma unroll
            for (int i = 0; i < 4; i++) {
                float v = sacc[nf][i] * 0.125f;
                if (diag) {
                    int col = nf * 8 + (lane & 3) * 2 + (i & 1);
                    int row = r0loc + ((i >> 1) ? 8 : 0);
                    if (col > row) v = -1e30f;
                }
                sacc[nf][i] = v;
                mx[i >> 1] = fmaxf(mx[i >> 1], v);
            }
        }
        #pragma unroll
        for (int o = 1; o < 4; o <<= 1) {
            mx[0] = fmaxf(mx[0], __shfl_xor_sync(0xffffffffu, mx[0], o));
            mx[1] = fmaxf(mx[1], __shfl_xor_sync(0xffffffffu, mx[1], o));
        }
        float fac[2], sum[2] = { 0.f, 0.f };
        #pragma unroll
        for (int j = 0; j < 2; j++) {
            float mnew = fmaxf(m[j], mx[j]);
            fac[j] = __expf(m[j] - mnew);
            m[j] = mnew;
        }
        #pragma unroll
        for (int nf = 0; nf < 8; nf++) {
            #pragma unroll
            for (int i = 0; i < 4; i++) {
                float p = __expf(sacc[nf][i] - m[i >> 1]);
                sacc[nf][i] = p;
                sum[i >> 1] += p;
            }
        }
        #pragma unroll
        for (int o = 1; o < 4; o <<= 1) {
            sum[0] += __shfl_xor_sync(0xffffffffu, sum[0], o);
            sum[1] += __shfl_xor_sync(0xffffffffu, sum[1], o);
        }
        #pragma unroll
        for (int j = 0; j < 2; j++) l[j] = l[j] * fac[j] + sum[j];
        #pragma unroll
        for (int nf = 0; nf < 8; nf++) {
            oacc[nf][0] *= fac[0]; oacc[nf][1] *= fac[0];
            oacc[nf][2] *= fac[1]; oacc[nf][3] *= fac[1];
        }

        #pragma unroll
        for (int t2 = 0; t2 < 4; ++t2) {
            float* p0 = sacc[2 * t2];
            float* p1 = sacc[2 * t2 + 1];
            uint32_t pa[4];
            pa[0] = packh2(p0[0], p0[1]);
            pa[1] = packh2(p0[2], p0[3]);
            pa[2] = packh2(p1[0], p1[1]);
            pa[3] = packh2(p1[2], p1[3]);

            uint32_t vf[4][4];
            #pragma unroll
            for (int nd = 0; nd < 4; ++nd) {
                uint32_t vrow = (uint32_t)(t2 * 16 + ((lane >> 4) << 3) + (lane & 7));
                uint32_t vcol = (uint32_t)(nd * 16 + (((lane >> 3) & 1) << 3));
                uint32_t vaddr = (vrow * AT_STRIDE + vcol) * 2;
                ldsm4t(vf[nd][0], vf[nd][1], vf[nd][2], vf[nd][3], sV + vaddr);
            }
            #pragma unroll
            for (int nd = 0; nd < 4; ++nd)
                #pragma unroll
                for (int o = 0; o < 2; ++o)
                    mma_f16(oacc[nd * 2 + o], pa[0], pa[1], pa[2], pa[3], vf[nd][o], vf[nd][o + 2]);
        }
        __syncthreads();
    }

    float inv0 = 1.f / l[0], inv1 = 1.f / l[1];
    long row0 = (long)(b * Sq_ + q0 + warp * 16 + (lane >> 2));
    long row1 = row0 + 8;
    #pragma unroll
    for (int nf = 0; nf < 8; nf++) {
        int col = h * DHq_ + nf * 8 + (lane & 3) * 2;
        *(__half2*)&O[row0 * Dq_ + col] = __floats2half2_rn(oacc[nf][0] * inv0, oacc[nf][1] * inv0);
        *(__half2*)&O[row1 * Dq_ + col] = __floats2half2_rn(oacc[nf][2] * inv1, oacc[nf][3] * inv1);
    }
}

// ---------------- launcher ----------------
extern "C" void kernel_launch(void* const* d_in, const int* in_sizes, int n_in,
                              void* d_out, int out_size) {
    const int*   x    = (const int*)  d_in[0];
    const float* tok  = (const float*)d_in[1];
    const float* pos  = (const float*)d_in[2];
    const float* Wq   = (const float*)d_in[3];
    const float* bq   = (const float*)d_in[4];
    const float* Wk   = (const float*)d_in[5];
    const float* bk   = (const float*)d_in[6];
    const float* Wv   = (const float*)d_in[7];
    const float* bv   = (const float*)d_in[8];
    const float* Wo   = (const float*)d_in[9];
    const float* bo   = (const float*)d_in[10];
    const float* ln1w = (const float*)d_in[11];
    const float* ln1b = (const float*)d_in[12];
    const float* ln2w = (const float*)d_in[13];
    const float* ln2b = (const float*)d_in[14];
    const float* W1   = (const float*)d_in[15];
    const float* b1   = (const float*)d_in[16];
    const float* W2   = (const float*)d_in[17];
    const float* b2   = (const float*)d_in[18];
    const float* lnfw = (const float*)d_in[19];
    const float* lnfb = (const float*)d_in[20];
    const float* Wout = (const float*)d_in[21];
    const float* bout = (const float*)d_in[22];
    float* out = (float*)d_out;

    float *h, *p;
    f16 *a, *q, *k, *v, *o, *f, *whi, *wlo;
    cudaGetSymbolAddress((void**)&h, g_h);
    cudaGetSymbolAddress((void**)&p, g_p);
    cudaGetSymbolAddress((void**)&a, g_a);
    cudaGetSymbolAddress((void**)&q, g_q);
    cudaGetSymbolAddress((void**)&k, g_k);
    cudaGetSymbolAddress((void**)&v, g_v);
    cudaGetSymbolAddress((void**)&o, g_o);
    cudaGetSymbolAddress((void**)&f, g_f);
    cudaGetSymbolAddress((void**)&whi, g_whi);
    cudaGetSymbolAddress((void**)&wlo, g_wlo);
    float* p0 = p;
    float* p1 = p + (size_t)Mq_ * Dq_;

    cudaFuncSetAttribute((const void*)gemm_kernel<0,true,1>,  cudaFuncAttributeMaxDynamicSharedMemorySize, GEMM_SMEM);
    cudaFuncSetAttribute((const void*)gemm_kernel<1,false,2>, cudaFuncAttributeMaxDynamicSharedMemorySize, GEMM_SMEM);
    cudaFuncSetAttribute((const void*)gemm_kernel<4,false,2>, cudaFuncAttributeMaxDynamicSharedMemorySize, GEMM_SMEM);
    cudaFuncSetAttribute((const void*)gemm_qkv_kernel, cudaFuncAttributeMaxDynamicSharedMemorySize, GEMM_SMEM);
    cudaFuncSetAttribute((const void*)attn_kernel, cudaFuncAttributeMaxDynamicSharedMemorySize, ATTN_SMEM);

    // ---- weight prep (batched) ----
    dim3 tb(32, 8);
    tsplit_sq_kernel<<<dim3(24, 24, 48), tb>>>(Wq, Wk, Wv, Wo, whi, wlo);
    tsplit_w1_kernel<<<dim3(Hq_ / 32, 24, 12), tb>>>(W1, whi, wlo);
    tsplit_w2_kernel<<<dim3(24, Hq_ / 32, 12), tb>>>(W2, whi, wlo);
    tsplit_out_kernel<<<dim3(VPAD_ / 32, 24), tb>>>(Wout, whi);

    embed_kernel<<<Mq_, 256>>>(x, tok, pos, h);

    dim3 gDs(Dq_ / 128, Mq_ / 128, 2);   // split-K2 grid for N=768
    dim3 gH(Hq_ / 128, Mq_ / 128);
    dim3 gVsw(Mq_ / 128, VPAD_ / 128);
    dim3 gQKV(Dq_ / 128, Mq_ / 128, 3);
    dim3 gAtt(Sq_ / 64, NHq_, Bq_);

    for (int i = 0; i < Lq_; ++i) {
        size_t off = (size_t)i * LWBLK;
        // ln1: first layer has no pending partials; later layers fold in FFN2 partials
        if (i == 0)
            ln_kernel<<<Mq_, 256>>>(h, ln1w, ln1b, a);
        else
            ln_sum_kernel<true><<<Mq_, 256>>>(h, p0, p1, ln1w + i * Dq_, ln1b + i * Dq_, a);

        gemm_qkv_kernel<<<gQKV, 256, GEMM_SMEM>>>(a, whi + off, wlo + off,
            bq + i * Dq_, bk + i * Dq_, bv + i * Dq_, q, k, v);
        attn_kernel<<<gAtt, 128, ATTN_SMEM>>>(q, k, v, o);

        // proj: split-K2 -> partial planes
        gemm_kernel<4,false,2><<<gDs, 256, GEMM_SMEM>>>(o, whi + off + 3 * WSQ, wlo + off + 3 * WSQ,
            bo + i * Dq_, p, nullptr, Dq_, Dq_, Dq_);

        // ln2 folds proj partials into h
        ln_sum_kernel<true><<<Mq_, 256>>>(h, p0, p1, ln2w + i * Dq_, ln2b + i * Dq_, a);

        gemm_kernel<1,false,2><<<gH, 256, GEMM_SMEM>>>(a, whi + off + 4 * WSQ, wlo + off + 4 * WSQ,
            b1 + i * Hq_, nullptr, f, Dq_, Hq_, Hq_);

        // FFN2: split-K2 -> partial planes (folded by next ln1 or final lnf)
        gemm_kernel<4,false,2><<<gDs, 256, GEMM_SMEM>>>(f, whi + off + 4 * WSQ + WSH, wlo + off + 4 * WSQ + WSH,
            b2 + i * Dq_, p, nullptr, Hq_, Dq_, Dq_);
    }

    ln_sum_kernel<false><<<Mq_, 256>>>(h, p0, p1, lnfw, lnfb, a);
    gemm_kernel<0,true,1><<<gVsw, 256, GEMM_SMEM>>>(a, whi + WOUT_OFF, nullptr,
        bout, out, nullptr, Dq_, VPAD_, Vq_);
}

// round 11
// speedup vs baseline: 1.9980x; 1.0321x over previous
#include <cuda_runtime.h>
#include <cuda_fp16.h>
#include <math.h>
#include <stdint.h>

// ---------------- problem constants ----------------
#define Bq_ 4
#define Sq_ 1024
#define Vq_ 50257
#define VPAD_ 50304
#define Dq_ 768
#define Hq_ 3072
#define NHq_ 12
#define DHq_ 64
#define Lq_ 12
#define Mq_ (Bq_*Sq_)   // 4096 rows

typedef __half f16;

#define WSQ (768UL*768UL)
#define WSH (768UL*3072UL)
#define LWBLK (4UL*WSQ + 2UL*WSH)
#define WOUT_OFF (LWBLK*12UL)
#define WTOT (WOUT_OFF + (size_t)VPAD_*Dq_)

// ---------------- scratch (device globals; no allocs allowed) ----------------
__device__ float g_h[Mq_*Dq_];
__device__ float g_p[3UL*Mq_*Dq_];          // split-K3 partial planes
__device__ f16 g_a[Mq_*Dq_];
__device__ f16 g_q[Mq_*Dq_];
__device__ f16 g_k[Mq_*Dq_];
__device__ f16 g_v[Mq_*Dq_];
__device__ f16 g_o[Mq_*Dq_];
__device__ f16 g_f[Mq_*Hq_];
__device__ f16 g_whi[WTOT], g_wlo[WTOT];

// ---------------- helpers ----------------
__device__ __forceinline__ uint32_t s2u(const void* p) {
    return (uint32_t)__cvta_generic_to_shared(p);
}
__device__ __forceinline__ void cp16(uint32_t d, const void* s) {
    asm volatile("cp.async.cg.shared.global [%0], [%1], 16;\n" :: "r"(d), "l"(s) : "memory");
}
#define CP_COMMIT asm volatile("cp.async.commit_group;\n" ::: "memory")
#define CP_WAIT1  asm volatile("cp.async.wait_group 1;\n" ::: "memory")
#define CP_WAIT0  asm volatile("cp.async.wait_group 0;\n" ::: "memory")

__device__ __forceinline__ void ldsm4(uint32_t &r0, uint32_t &r1, uint32_t &r2, uint32_t &r3,
                                      uint32_t addr) {
    asm volatile("ldmatrix.sync.aligned.m8n8.x4.shared.b16 {%0,%1,%2,%3}, [%4];\n"
        : "=r"(r0), "=r"(r1), "=r"(r2), "=r"(r3) : "r"(addr));
}
__device__ __forceinline__ void ldsm4t(uint32_t &r0, uint32_t &r1, uint32_t &r2, uint32_t &r3,
                                       uint32_t addr) {
    asm volatile("ldmatrix.sync.aligned.m8n8.x4.trans.shared.b16 {%0,%1,%2,%3}, [%4];\n"
        : "=r"(r0), "=r"(r1), "=r"(r2), "=r"(r3) : "r"(addr));
}
__device__ __forceinline__ void mma_f16(float* c, uint32_t a0, uint32_t a1, uint32_t a2, uint32_t a3,
                                        uint32_t b0, uint32_t b1) {
    asm volatile("mma.sync.aligned.m16n8k16.row.col.f32.f16.f16.f32 "
        "{%0,%1,%2,%3},{%4,%5,%6,%7},{%8,%9},{%0,%1,%2,%3};\n"
        : "+f"(c[0]), "+f"(c[1]), "+f"(c[2]), "+f"(c[3])
        : "r"(a0), "r"(a1), "r"(a2), "r"(a3), "r"(b0), "r"(b1));
}
__device__ __forceinline__ void split2h(float x, f16& h, f16& l) {
    h = __float2half_rn(x);
    l = __float2half_rn(x - __half2float(h));
}
__device__ __forceinline__ uint32_t packh2(float a, float b) {
    __half2 t = __floats2half2_rn(a, b);
    return *(uint32_t*)&t;
}

// ---------------- weight transpose + split (batched) ----------------
template<bool WRITE_LO>
__device__ __forceinline__ void tsplit_body(const float* __restrict__ W, f16* __restrict__ hi,
                                            f16* __restrict__ lo, int K, int Nsrc) {
    __shared__ float tile[32][33];
    int k0 = blockIdx.y * 32, n0 = blockIdx.x * 32;
    int tx = threadIdx.x, ty = threadIdx.y;
    #pragma unroll
    for (int i = 0; i < 4; i++) {
        int k = k0 + ty + i * 8, n = n0 + tx;
        tile[ty + i * 8][tx] = (n < Nsrc) ? W[(long)k * Nsrc + n] : 0.f;
    }
    __syncthreads();
    #pragma unroll
    for (int i = 0; i < 4; i++) {
        int n = n0 + ty + i * 8, k = k0 + tx;
        float v = tile[tx][ty + i * 8];
        f16 h, l; split2h(v, h, l);
        hi[(long)n * K + k] = h;
        if (WRITE_LO) lo[(long)n * K + k] = l;
    }
}

__global__ void tsplit_sq_kernel(const float* __restrict__ Wq, const float* __restrict__ Wk,
                                 const float* __restrict__ Wv, const float* __restrict__ Wo,
                                 f16* __restrict__ hi, f16* __restrict__ lo) {
    int z = blockIdx.z, layer = z >> 2, which = z & 3;
    const float* W = (which == 0 ? Wq : which == 1 ? Wk : which == 2 ? Wv : Wo) + (size_t)layer * WSQ;
    size_t off = (size_t)layer * LWBLK + (size_t)which * WSQ;
    if (which == 3)
        tsplit_body<false>(W, hi + off, nullptr, 768, 768);   // proj 1-term
    else
        tsplit_body<true>(W, hi + off, lo + off, 768, 768);
}
__global__ void tsplit_w1_kernel(const float* __restrict__ W1, f16* __restrict__ hi, f16* __restrict__ lo) {
    int layer = blockIdx.z;
    size_t off = (size_t)layer * LWBLK + 4 * WSQ;
    tsplit_body<true>(W1 + (size_t)layer * WSH, hi + off, lo + off, 768, Hq_);
}
__global__ void tsplit_w2_kernel(const float* __restrict__ W2, f16* __restrict__ hi, f16* __restrict__ lo) {
    int layer = blockIdx.z;
    size_t off = (size_t)layer * LWBLK + 4 * WSQ + WSH;
    tsplit_body<true>(W2 + (size_t)layer * WSH, hi + off, lo + off, Hq_, 768);
}
__global__ void tsplit_out_kernel(const float* __restrict__ W, f16* __restrict__ hi) {
    tsplit_body<false>(W, hi + WOUT_OFF, nullptr, 768, Vq_);
}

// ---------------- embedding ----------------
__global__ void embed_kernel(const int* __restrict__ x,
                             const float* __restrict__ tok,
                             const float* __restrict__ pos,
                             float* __restrict__ h) {
    int row = blockIdx.x;
    int s = row & (Sq_ - 1);
    int tid = x[row];
    const float* tp = tok + (long)tid * Dq_;
    const float* pp = pos + (long)s * Dq_;
    float* hp = h + (long)row * Dq_;
    for (int d = threadIdx.x; d < Dq_; d += 256)
        hp[d] = tp[d] + pp[d];
}

// ---------------- layernorm ----------------
__device__ __forceinline__ void ln_core(float v0, float v1, float v2,
                                        const float* __restrict__ w,
                                        const float* __restrict__ bb,
                                        f16* __restrict__ Y, long base, int t) {
    __shared__ float red[8];
    __shared__ float mean_s, inv_s;

    float s = v0 + v1 + v2;
    #pragma unroll
    for (int o = 16; o > 0; o >>= 1) s += __shfl_down_sync(0xffffffffu, s, o);
    if ((t & 31) == 0) red[t >> 5] = s;
    __syncthreads();
    if (t == 0) {
        float tot = 0.f;
        #pragma unroll
        for (int i = 0; i < 8; i++) tot += red[i];
        mean_s = tot * (1.0f / Dq_);
    }
    __syncthreads();
    float mean = mean_s;
    float d0 = v0 - mean, d1 = v1 - mean, d2 = v2 - mean;
    float q = d0 * d0 + d1 * d1 + d2 * d2;
    #pragma unroll
    for (int o = 16; o > 0; o >>= 1) q += __shfl_down_sync(0xffffffffu, q, o);
    if ((t & 31) == 0) red[t >> 5] = q;
    __syncthreads();
    if (t == 0) {
        float tot = 0.f;
        #pragma unroll
        for (int i = 0; i < 8; i++) tot += red[i];
        inv_s = rsqrtf(tot * (1.0f / Dq_) + 1e-5f);
    }
    __syncthreads();
    float inv = inv_s;
    Y[base + t]       = __float2half_rn(d0 * inv * w[t]       + bb[t]);
    Y[base + t + 256] = __float2half_rn(d1 * inv * w[t + 256] + bb[t + 256]);
    Y[base + t + 512] = __float2half_rn(d2 * inv * w[t + 512] + bb[t + 512]);
}

__global__ void ln_kernel(const float* __restrict__ X,
                          const float* __restrict__ w,
                          const float* __restrict__ bb,
                          f16* __restrict__ Y) {
    int row = blockIdx.x;
    const float* x = X + (long)row * Dq_;
    int t = threadIdx.x;
    ln_core(x[t], x[t + 256], x[t + 512], w, bb, Y, (long)row * Dq_, t);
}

// residual-sum + layernorm: h' = h + P0 + P1 + P2 (optional write-back), Y = LN(h')
template<bool WRITEH>
__global__ void ln_sum_kernel(float* __restrict__ H,
                              const float* __restrict__ P0, const float* __restrict__ P1,
                              const float* __restrict__ P2,
                              const float* __restrict__ w, const float* __restrict__ bb,
                              f16* __restrict__ Y) {
    int row = blockIdx.x;
    long base = (long)row * Dq_;
    int t = threadIdx.x;
    float v0 = H[base + t]       + P0[base + t]       + P1[base + t]       + P2[base + t];
    float v1 = H[base + t + 256] + P0[base + t + 256] + P1[base + t + 256] + P2[base + t + 256];
    float v2 = H[base + t + 512] + P0[base + t + 512] + P1[base + t + 512] + P2[base + t + 512];
    if (WRITEH) {
        H[base + t]       = v0;
        H[base + t + 256] = v1;
        H[base + t + 512] = v2;
    }
    ln_core(v0, v1, v2, w, bb, Y, base, t);
}

// ---------------- fp16 HMMA GEMM, 3-stage pipeline ----------------
// C = A[MxK](f16) * (Bh [+ Bl])^T + bias
// EPI: 0 = fp32 C+bias; 1 = GELU -> f16; 3 = f16 out; 4 = split-K3 fp32 partial plane
#define GEMM_SMEM (3 * 3 * 128 * 40 * 2)   // 92160 max

template<int EPI, bool SWAP, int NTERMS>
__device__ __forceinline__ void gemm_body(
    const f16* __restrict__ A,
    const f16* __restrict__ Bhi, const f16* __restrict__ Blo,
    const float* __restrict__ bias,
    float* __restrict__ C, f16* __restrict__ C16,
    int K, int N, int Nout)
{
    const int ARR = 1 + NTERMS;
    extern __shared__ f16 sm[];
    uint32_t smb = s2u(sm);
    int tid = threadIdx.x;
    int bm = (SWAP ? blockIdx.x : blockIdx.y) * 128;
    int bn = (SWAP ? blockIdx.y : blockIdx.x) * 128;
    int warp = tid >> 5, lane = tid & 31;
    int wm = warp >> 2, wn = warp & 3;

    int kz = (EPI == 4) ? blockIdx.z : 0;
    int Keff = (EPI == 4) ? (K / 3) : K;
    long koff = (long)kz * Keff;

    float acc[4][4][4];
    #pragma unroll
    for (int i = 0; i < 4; i++)
        #pragma unroll
        for (int j = 0; j < 4; j++)
            #pragma unroll
            for (int k = 0; k < 4; k++) acc[i][j][k] = 0.f;

    const f16* srcs[3] = { A + (long)bm * K + koff, Bhi + (long)bn * K + koff,
                           (NTERMS == 2) ? Blo + (long)bn * K + koff : nullptr };

    auto issue = [&](int b, int kt) {
        int k0 = kt * 32;
        #pragma unroll
        for (int arr = 0; arr < ARR; arr++) {
            #pragma unroll
            for (int i = 0; i < 2; i++) {
                int ch = tid + i * 256;
                int row = ch >> 2, cg = ch & 3;
                uint32_t dst = smb + ((((b * ARR + arr) * 128 + row) * 40) + cg * 8) * 2;
                cp16(dst, srcs[arr] + (long)row * K + k0 + cg * 8);
            }
        }
    };

    int nk = Keff >> 5;
    issue(0, 0); CP_COMMIT;
    issue(1, 1); CP_COMMIT;

    int lrow = lane & 15, lcg = lane >> 4;

    for (int kt = 0; kt < nk; ++kt) {
        int cur = kt % 3;
        if (kt + 1 < nk) { CP_WAIT1; } else { CP_WAIT0; }
        __syncthreads();
        if (kt + 2 < nk) { issue((kt + 2) % 3, kt + 2); CP_COMMIT; }

        #pragma unroll
        for (int ks = 0; ks < 2; ++ks) {
            uint32_t af[4][4];
            #pragma unroll
            for (int mf = 0; mf < 4; mf++) {
                int row = wm * 64 + mf * 16 + lrow;
                int col = ks * 16 + lcg * 8;
                uint32_t a0 = smb + ((((cur * ARR + 0) * 128 + row) * 40) + col) * 2;
                ldsm4(af[mf][0], af[mf][1], af[mf][2], af[mf][3], a0);
            }
            uint32_t bh[2][4], bl[2][4];
            #pragma unroll
            for (int nf2 = 0; nf2 < 2; nf2++) {
                int row = wn * 32 + nf2 * 16 + lrow;
                int col = ks * 16 + lcg * 8;
                uint32_t b0 = smb + ((((cur * ARR + 1) * 128 + row) * 40) + col) * 2;
                ldsm4(bh[nf2][0], bh[nf2][1], bh[nf2][2], bh[nf2][3], b0);
                if (NTERMS == 2) {
                    uint32_t b1 = smb + ((((cur * ARR + 2) * 128 + row) * 40) + col) * 2;
                    ldsm4(bl[nf2][0], bl[nf2][1], bl[nf2][2], bl[nf2][3], b1);
                }
            }
            #pragma unroll
            for (int mf = 0; mf < 4; mf++)
                #pragma unroll
                for (int nf = 0; nf < 4; nf++) {
                    int g = nf >> 1, o = nf & 1;
                    mma_f16(acc[mf][nf], af[mf][0], af[mf][1], af[mf][2], af[mf][3],
                            bh[g][o], bh[g][o + 2]);
                }
            if (NTERMS == 2) {
                #pragma unroll
                for (int mf = 0; mf < 4; mf++)
                    #pragma unroll
                    for (int nf = 0; nf < 4; nf++) {
                        int g = nf >> 1, o = nf & 1;
                        mma_f16(acc[mf][nf], af[mf][0], af[mf][1], af[mf][2], af[mf][3],
                                bl[g][o], bl[g][o + 2]);
                    }
            }
        }
    }

    float* Cp = (EPI == 4) ? (C + (size_t)kz * Mq_ * (size_t)Nout) : C;

    int r = lane >> 2, c2 = (lane & 3) * 2;
    #pragma unroll
    for (int mf = 0; mf < 4; mf++) {
        #pragma unroll
        for (int nf = 0; nf < 4; nf++) {
            #pragma unroll
            for (int half2_ = 0; half2_ < 2; half2_++) {
                long row = bm + wm * 64 + mf * 16 + r + half2_ * 8;
                #pragma unroll
                for (int e = 0; e < 2; e++) {
                    int col = bn + wn * 32 + nf * 8 + c2 + e;
                    if (col < Nout) {
                        float v = acc[mf][nf][half2_ * 2 + e];
                        if (EPI == 4) {
                            if (kz == 0) v += bias[col];
                            Cp[row * (long)Nout + col] = v;
                        } else {
                            v += bias[col];
                            if (EPI == 1 || EPI == 3) {
                                if (EPI == 1)
                                    v = 0.5f * v * (1.f + erff(v * 0.70710678118654752f));
                                C16[row * N + col] = __float2half_rn(v);
                            } else {
                                Cp[row * (long)Nout + col] = v;
                            }
                        }
                    }
                }
            }
        }
    }
}

template<int EPI, bool SWAP, int NTERMS>
__global__ __launch_bounds__(256, 1) void gemm_kernel(
    const f16* __restrict__ A,
    const f16* __restrict__ Bhi, const f16* __restrict__ Blo,
    const float* __restrict__ bias,
    float* __restrict__ C, f16* __restrict__ C16,
    int K, int N, int Nout)
{
    gemm_body<EPI, SWAP, NTERMS>(A, Bhi, Blo, bias, C, C16, K, N, Nout);
}

__global__ __launch_bounds__(256, 1) void gemm_qkv_kernel(
    const f16* __restrict__ A,
    const f16* __restrict__ whi, const f16* __restrict__ wlo,
    const float* __restrict__ bq, const float* __restrict__ bk, const float* __restrict__ bv,
    f16* __restrict__ q, f16* __restrict__ k, f16* __restrict__ v)
{
    int z = blockIdx.z;
    const f16* Bh = whi + (size_t)z * WSQ;
    const f16* Bl = wlo + (size_t)z * WSQ;
    const float* bias = (z == 0) ? bq : (z == 1) ? bk : bv;
    f16* C16 = (z == 0) ? q : (z == 1) ? k : v;
    gemm_body<3, false, 2>(A, Bh, Bl, bias, nullptr, C16, Dq_, Dq_, Dq_);
}

// ---------------- HMMA flash attention, fp16, double-buffered, heavy-first ----------------
#define AT_STRIDE 72
#define AT_TILE (64 * AT_STRIDE)
#define ATTN_SMEM (5 * AT_TILE * 2)   // Q + 2x(K,V) = 46080

__global__ __launch_bounds__(128, 4) void attn_kernel(
    const f16* __restrict__ Qg, const f16* __restrict__ Kg, const f16* __restrict__ Vg,
    f16* __restrict__ O)
{
    extern __shared__ f16 asm_[];
    uint32_t smb = s2u(asm_);
    uint32_t sQ = smb;

    int t = threadIdx.x, warp = t >> 5, lane = t & 31;
    // LPT: heavy q-tiles (most K-tiles) get scheduled first
    int qt = (int)gridDim.x - 1 - (int)blockIdx.x;
    int q0 = qt * 64, h = blockIdx.y, b = blockIdx.z;

    long rowbase = (long)(b * Sq_ + q0) * Dq_ + h * DHq_;

    auto issue_kv = [&](int buf, int jt) {
        uint32_t sK = smb + (1 + buf * 2) * AT_TILE * 2;
        uint32_t sV = sK + AT_TILE * 2;
        long kbase = (long)(b * Sq_ + jt * 64) * Dq_ + h * DHq_;
        #pragma unroll
        for (int i = 0; i < 4; i++) {
            int idx = t + i * 128;
            int row = idx >> 3, ch = idx & 7;
            uint32_t doff = (uint32_t)(row * AT_STRIDE + ch * 8) * 2;
            long goff = kbase + (long)row * Dq_ + ch * 8;
            cp16(sK + doff, Kg + goff);
            cp16(sV + doff, Vg + goff);
        }
    };

    #pragma unroll
    for (int i = 0; i < 4; i++) {
        int idx = t + i * 128;
        int row = idx >> 3, ch = idx & 7;
        uint32_t doff = (uint32_t)(row * AT_STRIDE + ch * 8) * 2;
        cp16(sQ + doff, Qg + rowbase + (long)row * Dq_ + ch * 8);
    }
    issue_kv(0, 0);
    CP_COMMIT;

    float m[2] = { -1e30f, -1e30f }, l[2] = { 0.f, 0.f };
    float oacc[8][4];
    #pragma unroll
    for (int i = 0; i < 8; i++)
        #pragma unroll
        for (int j = 0; j < 4; j++) oacc[i][j] = 0.f;

    int lrow = lane & 15, lcg = lane >> 4;
    int ntiles = q0 / 64 + 1;

    for (int it = 0; it < ntiles; ++it) {
        if (it + 1 < ntiles) { issue_kv((it + 1) & 1, it + 1); CP_COMMIT; CP_WAIT1; }
        else                 { CP_WAIT0; }
        __syncthreads();

        uint32_t sK = smb + (1 + (it & 1) * 2) * AT_TILE * 2;
        uint32_t sV = sK + AT_TILE * 2;
        int j0 = it * 64;

        float sacc[8][4];
        #pragma unroll
        for (int i = 0; i < 8; i++)
            #pragma unroll
            for (int j = 0; j < 4; j++) sacc[i][j] = 0.f;

        #pragma unroll
        for (int ks = 0; ks < 4; ++ks) {
            int acol = ks * 16 + lcg * 8;
            uint32_t qf[4];
            uint32_t qaddr = (uint32_t)((warp * 16 + lrow) * AT_STRIDE + acol) * 2;
            ldsm4(qf[0], qf[1], qf[2], qf[3], sQ + qaddr);
            uint32_t kf[4][4];
            #pragma unroll
            for (int kg = 0; kg < 4; ++kg) {
                uint32_t kaddr = (uint32_t)((kg * 16 + lrow) * AT_STRIDE + acol) * 2;
                ldsm4(kf[kg][0], kf[kg][1], kf[kg][2], kf[kg][3], sK + kaddr);
            }
            #pragma unroll
            for (int kg = 0; kg < 4; ++kg)
                #pragma unroll
                for (int o = 0; o < 2; ++o)
                    mma_f16(sacc[kg * 2 + o], qf[0], qf[1], qf[2], qf[3], kf[kg][o], kf[kg][o + 2]);
        }

        int r0loc = warp * 16 + (lane >> 2);
        bool diag = (j0 == q0);
        float mx[2] = { -1e30f, -1e30f };
        #pragma unroll
        for (int nf = 0; nf < 8; nf++) {
            #pragma unroll
            for (int i = 0; i < 4; i++) {
                float v = sacc[nf][i] * 0.125f;
                if (diag) {
                    int col = nf * 8 + (lane & 3) * 2 + (i & 1);
                    int row = r0loc + ((i >> 1) ? 8 : 0);
                    if (col > row) v = -1e30f;
                }
                sacc[nf][i] = v;
                mx[i >> 1] = fmaxf(mx[i >> 1], v);
            }
        }
        #pragma unroll
        for (int o = 1; o < 4; o <<= 1) {
            mx[0] = fmaxf(mx[0], __shfl_xor_sync(0xffffffffu, mx[0], o));
            mx[1] = fmaxf(mx[1], __shfl_xor_sync(0xffffffffu, mx[1], o));
        }
        float fac[2], sum[2] = { 0.f, 0.f };
        #pragma unroll
        for (int j = 0; j < 2; j++) {
            float mnew = fmaxf(m[j], mx[j]);
            fac[j] = __expf(m[j] - mnew);
            m[j] = mnew;
        }
        #pragma unroll
        for (int nf = 0; nf < 8; nf++) {
            #pragma unroll
            for (int i = 0; i < 4; i++) {
                float p = __expf(sacc[nf][i] - m[i >> 1]);
                sacc[nf][i] = p;
                sum[i >> 1] += p;
            }
        }
        #pragma unroll
        for (int o = 1; o < 4; o <<= 1) {
            sum[0] += __shfl_xor_sync(0xffffffffu, sum[0], o);
            sum[1] += __shfl_xor_sync(0xffffffffu, sum[1], o);
        }
        #pragma unroll
        for (int j = 0; j < 2; j++) l[j] = l[j] * fac[j] + sum[j];
        #pragma unroll
        for (int nf = 0; nf < 8; nf++) {
            oacc[nf][0] *= fac[0]; oacc[nf][1] *= fac[0];
            oacc[nf][2] *= fac[1]; oacc[nf][3] *= fac[1];
        }

        #pragma unroll
        for (int t2 = 0; t2 < 4; ++t2) {
            float* p0 = sacc[2 * t2];
            float* p1 = sacc[2 * t2 + 1];
            uint32_t pa[4];
            pa[0] = packh2(p0[0], p0[1]);
            pa[1] = packh2(p0[2], p0[3]);
            pa[2] = packh2(p1[0], p1[1]);
            pa[3] = packh2(p1[2], p1[3]);

            uint32_t vf[4][4];
            #pragma unroll
            for (int nd = 0; nd < 4; ++nd) {
                uint32_t vrow = (uint32_t)(t2 * 16 + ((lane >> 4) << 3) + (lane & 7));
                uint32_t vcol = (uint32_t)(nd * 16 + (((lane >> 3) & 1) << 3));
                uint32_t vaddr = (vrow * AT_STRIDE + vcol) * 2;
                ldsm4t(vf[nd][0], vf[nd][1], vf[nd][2], vf[nd][3], sV + vaddr);
            }
            #pragma unroll
            for (int nd = 0; nd < 4; ++nd)
                #pragma unroll
                for (int o = 0; o < 2; ++o)
                    mma_f16(oacc[nd * 2 + o], pa[0], pa[1], pa[2], pa[3], vf[nd][o], vf[nd][o + 2]);
        }
        __syncthreads();
    }

    float inv0 = 1.f / l[0], inv1 = 1.f / l[1];
    long row0 = (long)(b * Sq_ + q0 + warp * 16 + (lane >> 2));
    long row1 = row0 + 8;
    #pragma unroll
    for (int nf = 0; nf < 8; nf++) {
        int col = h * DHq_ + nf * 8 + (lane & 3) * 2;
        *(__half2*)&O[row0 * Dq_ + col] = __floats2half2_rn(oacc[nf][0] * inv0, oacc[nf][1] * inv0);
        *(__half2*)&O[row1 * Dq_ + col] = __floats2half2_rn(oacc[nf][2] * inv1, oacc[nf][3] * inv1);
    }
}

// ---------------- launcher ----------------
extern "C" void kernel_launch(void* const* d_in, const int* in_sizes, int n_in,
                              void* d_out, int out_size) {
    const int*   x    = (const int*)  d_in[0];
    const float* tok  = (const float*)d_in[1];
    const float* pos  = (const float*)d_in[2];
    const float* Wq   = (const float*)d_in[3];
    const float* bq   = (const float*)d_in[4];
    const float* Wk   = (const float*)d_in[5];
    const float* bk   = (const float*)d_in[6];
    const float* Wv   = (const float*)d_in[7];
    const float* bv   = (const float*)d_in[8];
    const float* Wo   = (const float*)d_in[9];
    const float* bo   = (const float*)d_in[10];
    const float* ln1w = (const float*)d_in[11];
    const float* ln1b = (const float*)d_in[12];
    const float* ln2w = (const float*)d_in[13];
    const float* ln2b = (const float*)d_in[14];
    const float* W1   = (const float*)d_in[15];
    const float* b1   = (const float*)d_in[16];
    const float* W2   = (const float*)d_in[17];
    const float* b2   = (const float*)d_in[18];
    const float* lnfw = (const float*)d_in[19];
    const float* lnfb = (const float*)d_in[20];
    const float* Wout = (const float*)d_in[21];
    const float* bout = (const float*)d_in[22];
    float* out = (float*)d_out;

    float *h, *p;
    f16 *a, *q, *k, *v, *o, *f, *whi, *wlo;
    cudaGetSymbolAddress((void**)&h, g_h);
    cudaGetSymbolAddress((void**)&p, g_p);
    cudaGetSymbolAddress((void**)&a, g_a);
    cudaGetSymbolAddress((void**)&q, g_q);
    cudaGetSymbolAddress((void**)&k, g_k);
    cudaGetSymbolAddress((void**)&v, g_v);
    cudaGetSymbolAddress((void**)&o, g_o);
    cudaGetSymbolAddress((void**)&f, g_f);
    cudaGetSymbolAddress((void**)&whi, g_whi);
    cudaGetSymbolAddress((void**)&wlo, g_wlo);
    float* p0 = p;
    float* p1 = p + (size_t)Mq_ * Dq_;
    float* p2 = p + 2 * (size_t)Mq_ * Dq_;

    cudaFuncSetAttribute((const void*)gemm_kernel<0,true,1>,  cudaFuncAttributeMaxDynamicSharedMemorySize, GEMM_SMEM);
    cudaFuncSetAttribute((const void*)gemm_kernel<1,false,2>, cudaFuncAttributeMaxDynamicSharedMemorySize, GEMM_SMEM);
    cudaFuncSetAttribute((const void*)gemm_kernel<4,false,1>, cudaFuncAttributeMaxDynamicSharedMemorySize, GEMM_SMEM);
    cudaFuncSetAttribute((const void*)gemm_kernel<4,false,2>, cudaFuncAttributeMaxDynamicSharedMemorySize, GEMM_SMEM);
    cudaFuncSetAttribute((const void*)gemm_qkv_kernel, cudaFuncAttributeMaxDynamicSharedMemorySize, GEMM_SMEM);
    cudaFuncSetAttribute((const void*)attn_kernel, cudaFuncAttributeMaxDynamicSharedMemorySize, ATTN_SMEM);

    // ---- weight prep (batched) ----
    dim3 tb(32, 8);
    tsplit_sq_kernel<<<dim3(24, 24, 48), tb>>>(Wq, Wk, Wv, Wo, whi, wlo);
    tsplit_w1_kernel<<<dim3(Hq_ / 32, 24, 12), tb>>>(W1, whi, wlo);
    tsplit_w2_kernel<<<dim3(24, Hq_ / 32, 12), tb>>>(W2, whi, wlo);
    tsplit_out_kernel<<<dim3(VPAD_ / 32, 24), tb>>>(Wout, whi);

    embed_kernel<<<Mq_, 256>>>(x, tok, pos, h);

    dim3 gDs3(Dq_ / 128, Mq_ / 128, 3);  // split-K3 grid for N=768
    dim3 gH(Hq_ / 128, Mq_ / 128);
    dim3 gVsw(Mq_ / 128, VPAD_ / 128);
    dim3 gQKV(Dq_ / 128, Mq_ / 128, 3);
    dim3 gAtt(Sq_ / 64, NHq_, Bq_);

    for (int i = 0; i < Lq_; ++i) {
        size_t off = (size_t)i * LWBLK;
        if (i == 0)
            ln_kernel<<<Mq_, 256>>>(h, ln1w, ln1b, a);
        else
            ln_sum_kernel<true><<<Mq_, 256>>>(h, p0, p1, p2, ln1w + i * Dq_, ln1b + i * Dq_, a);

        gemm_qkv_kernel<<<gQKV, 256, GEMM_SMEM>>>(a, whi + off, wlo + off,
            bq + i * Dq_, bk + i * Dq_, bv + i * Dq_, q, k, v);
        attn_kernel<<<gAtt, 128, ATTN_SMEM>>>(q, k, v, o);

        // proj: 1-term weights, split-K3 -> partial planes
        gemm_kernel<4,false,1><<<gDs3, 256, GEMM_SMEM>>>(o, whi + off + 3 * WSQ, nullptr,
            bo + i * Dq_, p, nullptr, Dq_, Dq_, Dq_);

        ln_sum_kernel<true><<<Mq_, 256>>>(h, p0, p1, p2, ln2w + i * Dq_, ln2b + i * Dq_, a);

        gemm_kernel<1,false,2><<<gH, 256, GEMM_SMEM>>>(a, whi + off + 4 * WSQ, wlo + off + 4 * WSQ,
            b1 + i * Hq_, nullptr, f, Dq_, Hq_, Hq_);

        // FFN2: 2-term, split-K3 -> partial planes
        gemm_kernel<4,false,2><<<gDs3, 256, GEMM_SMEM>>>(f, whi + off + 4 * WSQ + WSH, wlo + off + 4 * WSQ + WSH,
            b2 + i * Dq_, p, nullptr, Hq_, Dq_, Dq_);
    }

    ln_sum_kernel<false><<<Mq_, 256>>>(h, p0, p1, p2, lnfw, lnfb, a);
    gemm_kernel<0,true,1><<<gVsw, 256, GEMM_SMEM>>>(a, whi + WOUT_OFF, nullptr,
        bout, out, nullptr, Dq_, VPAD_, Vq_);
}